// round 7
// baseline (speedup 1.0000x reference)
#include <cuda_runtime.h>
#include <cuda_bf16.h>
#include <cstdint>

// Problem constants (fixed by the dataset)
#define NN 100000
#define EE 1600000
#define DH 128

// ---------------- scratch (device globals; no allocation allowed) -------------
__device__ __nv_bfloat16 g_xbf[NN * DH];
__device__ __nv_bfloat16 g_h1bf[NN * DH];
__device__ uint32_t g_wp[4 * 8192];      // 4 matrices, bf16-pair packed [k2][n]
__device__ int   g_counts[NN];
__device__ int   g_row[NN + 1];
__device__ int   g_cursor[NN];
__device__ int   g_csr[EE];
__device__ int   g_bsums[128];
__device__ float g_invdeg[NN];
__device__ float g_pl[NN * 2];
__device__ float g_pr[NN * 2];

__device__ __forceinline__ uint32_t packbf(float a, float b) {
    __nv_bfloat162 h = __floats2bfloat162_rn(a, b);   // .x = a (low), .y = b (high)
    return *reinterpret_cast<uint32_t*>(&h);
}

// ---------------- prep: zero counts + cast x to bf16 + pack weights ----------
#define XBLK 25000   // ceil(NN*64 / 256)

__global__ void k_prep(const float* __restrict__ x,
                       const float* __restrict__ wl0, const float* __restrict__ wr0,
                       const float* __restrict__ wl1, const float* __restrict__ wr1) {
    int gi = blockIdx.x * 256 + threadIdx.x;
    if (blockIdx.x < XBLK) {
        if (gi < NN) g_counts[gi] = 0;
        if (gi < NN * 64) {
            float2 v = ((const float2*)x)[gi];
            reinterpret_cast<uint32_t*>(g_xbf)[gi] = packbf(v.x, v.y);
        }
    } else {
        int i = (blockIdx.x - XBLK) * 256 + threadIdx.x;   // 0..32767
        int m = i >> 13, idx = i & 8191;
        int n = idx & 127, k2 = idx >> 7;
        const float* s = (m == 0) ? wl0 : (m == 1) ? wr0 : (m == 2) ? wl1 : wr1;
        float2 v = *(const float2*)(s + n * 128 + 2 * k2);
        g_wp[m * 8192 + k2 * 128 + n] = packbf(v.x, v.y);
    }
}

// ---------------- CSR build --------------------------------------------------
__global__ void k_hist(const int* __restrict__ dst) {
    int e = blockIdx.x * blockDim.x + threadIdx.x;
    if (e < EE) atomicAdd(&g_counts[dst[e]], 1);
}

__global__ void k_scan1() {
    __shared__ int sd[1024];
    int t = threadIdx.x;
    int g = blockIdx.x * 1024 + t;
    int v = (g < NN) ? g_counts[g] : 0;
    sd[t] = v;
    __syncthreads();
    #pragma unroll
    for (int off = 1; off < 1024; off <<= 1) {
        int x = (t >= off) ? sd[t - off] : 0;
        __syncthreads();
        sd[t] += x;
        __syncthreads();
    }
    if (g < NN) g_row[g] = sd[t] - v;   // exclusive within block
    if (t == 1023) g_bsums[blockIdx.x] = sd[t];
}

// scan of block sums done redundantly per block (98 values, trivial) + finalize
__global__ void k_scan3() {
    __shared__ int sb[128];
    int t = threadIdx.x;
    if (t < 128) sb[t] = (t < 98) ? g_bsums[t] : 0;
    __syncthreads();
    #pragma unroll
    for (int off = 1; off < 128; off <<= 1) {
        int x = (t < 128 && t >= off) ? sb[t - off] : 0;
        __syncthreads();
        if (t < 128) sb[t] += x;
        __syncthreads();
    }
    int myoff = (blockIdx.x == 0) ? 0 : sb[blockIdx.x - 1];   // inclusive -> exclusive
    int g = blockIdx.x * 1024 + t;
    if (g < NN) {
        int r = g_row[g] + myoff;
        g_row[g] = r;
        g_cursor[g] = r;
        int c = g_counts[g];
        g_invdeg[g] = 1.0f / (float)(c > 0 ? c : 1);
    }
    if (blockIdx.x == 0 && t == 0) g_row[NN] = EE;
}

__global__ void k_scatter(const int* __restrict__ src, const int* __restrict__ dst) {
    int e = blockIdx.x * blockDim.x + threadIdx.x;
    if (e < EE) {
        int d = dst[e];
        int pos = atomicAdd(&g_cursor[d], 1);
        g_csr[pos] = src[e];
    }
}

// ---------------- fused layer: bf16 mean-agg + bf16 MMA (+ projection) -------
// out = relu(mean_nbr(hin)@Wl^T + b + hin@Wr^T)
// MODE 0: write 128-dim bf16 result to hout.
// MODE 1: project with wl2/wr2 -> g_pl/g_pr [N,2]; hout untouched.
// Block: M=128 x N=128, 8 warps (4 M x 2 N). K=256 as two K=128 chunks,
// mma m16n8k16 bf16, fp32 accumulate. Gather unrolled x4 for MLP.
#define XS2 68    // uint32 (bf16x2) stride: A-frag reads conflict-free
#define WS2 136   // uint32 stride: B-frag reads conflict-free

__device__ __forceinline__ void mma_bf16(float* c, const uint32_t* a, const uint32_t* b) {
    asm volatile(
        "mma.sync.aligned.m16n8k16.row.col.f32.bf16.bf16.f32 "
        "{%0,%1,%2,%3}, {%4,%5,%6,%7}, {%8,%9}, {%0,%1,%2,%3};"
        : "+f"(c[0]), "+f"(c[1]), "+f"(c[2]), "+f"(c[3])
        : "r"(a[0]), "r"(a[1]), "r"(a[2]), "r"(a[3]), "r"(b[0]), "r"(b[1]));
}

__device__ __forceinline__ void addbf(float4& a, uint2 v) {
    float2 f0 = __bfloat1622float2(*(__nv_bfloat162*)&v.x);
    float2 f1 = __bfloat1622float2(*(__nv_bfloat162*)&v.y);
    a.x += f0.x; a.y += f0.y; a.z += f1.x; a.w += f1.y;
}

template <int MODE>
__global__ void __launch_bounds__(256, 2) k_layer(
    const __nv_bfloat16* __restrict__ hin,
    const uint32_t* __restrict__ wpL, const uint32_t* __restrict__ wpR,
    const float* __restrict__ bias, __nv_bfloat16* __restrict__ hout,
    const float* __restrict__ wl2, const float* __restrict__ wr2) {
    extern __shared__ uint32_t sm[];
    uint32_t* sW = sm;                    // [64][WS2]
    uint32_t* sX = sm + 64 * WS2;         // [128][XS2]

    int tid = threadIdx.x;
    int lane = tid & 31, wid = tid >> 5;
    int g = lane >> 2, t = lane & 3;
    int mw = wid & 3, nw = wid >> 2;
    int nodeBase = blockIdx.x * 128;

    float acc[2][8][4];
    #pragma unroll
    for (int i = 0; i < 2; i++)
        #pragma unroll
        for (int j = 0; j < 8; j++)
            #pragma unroll
            for (int q = 0; q < 4; q++) acc[i][j][q] = 0.f;

    #pragma unroll
    for (int chunk = 0; chunk < 2; chunk++) {
        // ---- stage X ----
        if (chunk == 0) {
            // fused mean aggregation, 4-way unrolled for memory-level parallelism
            const uint2* hin2 = (const uint2*)hin;
            for (int p = 0; p < 16; p++) {
                int r = wid * 16 + p;
                int node = nodeBase + r;
                float4 a0 = make_float4(0.f, 0.f, 0.f, 0.f);
                float4 a1 = a0, a2 = a0, a3 = a0;
                if (node < NN) {
                    int e = g_row[node], e1 = g_row[node + 1];
                    for (; e + 3 < e1; e += 4) {
                        int sa = g_csr[e],     sb = g_csr[e + 1];
                        int sc = g_csr[e + 2], sd = g_csr[e + 3];
                        uint2 va = hin2[(size_t)sa * 32 + lane];
                        uint2 vb = hin2[(size_t)sb * 32 + lane];
                        uint2 vc = hin2[(size_t)sc * 32 + lane];
                        uint2 vd = hin2[(size_t)sd * 32 + lane];
                        addbf(a0, va); addbf(a1, vb); addbf(a2, vc); addbf(a3, vd);
                    }
                    if (e + 1 < e1) {
                        int sa = g_csr[e], sb = g_csr[e + 1];
                        uint2 va = hin2[(size_t)sa * 32 + lane];
                        uint2 vb = hin2[(size_t)sb * 32 + lane];
                        addbf(a0, va); addbf(a1, vb);
                        e += 2;
                    }
                    if (e < e1) {
                        uint2 va = hin2[(size_t)g_csr[e] * 32 + lane];
                        addbf(a0, va);
                    }
                    float sc4 = g_invdeg[node];
                    a0.x = (a0.x + a1.x + a2.x + a3.x) * sc4;
                    a0.y = (a0.y + a1.y + a2.y + a3.y) * sc4;
                    a0.z = (a0.z + a1.z + a2.z + a3.z) * sc4;
                    a0.w = (a0.w + a1.w + a2.w + a3.w) * sc4;
                }
                sX[r * XS2 + lane * 2]     = packbf(a0.x, a0.y);
                sX[r * XS2 + lane * 2 + 1] = packbf(a0.z, a0.w);
            }
        } else {
            // root path: coalesced bf16 rows
            for (int i = tid; i < 128 * 64; i += 256) {
                int r = i >> 6, c2 = i & 63;
                int n = nodeBase + r;
                uint32_t v = 0;
                if (n < NN) v = ((const uint32_t*)hin)[(size_t)n * 64 + c2];
                sX[r * XS2 + c2] = v;
            }
        }
        // ---- stage W (pre-packed bf16 pairs, straight copy) ----
        const uint32_t* wp = chunk ? wpR : wpL;
        for (int i = tid; i < 64 * 128; i += 256) {
            int k2 = i >> 7, n = i & 127;
            sW[k2 * WS2 + n] = wp[i];
        }
        __syncthreads();

        #pragma unroll
        for (int ks = 0; ks < 8; ks++) {
            int k02 = ks * 8;   // col2 units (16 k-elements = 8 pairs)
            uint32_t a[2][4], b[8][2];
            #pragma unroll
            for (int i = 0; i < 2; i++) {
                int row = mw * 32 + i * 16 + g;
                a[i][0] = sX[row * XS2 + k02 + t];
                a[i][1] = sX[(row + 8) * XS2 + k02 + t];
                a[i][2] = sX[row * XS2 + k02 + t + 4];
                a[i][3] = sX[(row + 8) * XS2 + k02 + t + 4];
            }
            #pragma unroll
            for (int j = 0; j < 8; j++) {
                int col = nw * 64 + j * 8 + g;
                b[j][0] = sW[(k02 + t) * WS2 + col];
                b[j][1] = sW[(k02 + t + 4) * WS2 + col];
            }
            #pragma unroll
            for (int i = 0; i < 2; i++)
                #pragma unroll
                for (int j = 0; j < 8; j++)
                    mma_bf16(acc[i][j], a[i], b[j]);
        }
        __syncthreads();
    }

    if (MODE == 0) {
        // epilogue: bias + relu -> bf16 hout
        #pragma unroll
        for (int i = 0; i < 2; i++) {
            int row0 = nodeBase + mw * 32 + i * 16 + g;
            #pragma unroll
            for (int j = 0; j < 8; j++) {
                int col = nw * 64 + j * 8 + 2 * t;
                float2 bb = *(const float2*)(bias + col);
                float v0x = fmaxf(acc[i][j][0] + bb.x, 0.f);
                float v0y = fmaxf(acc[i][j][1] + bb.y, 0.f);
                float v1x = fmaxf(acc[i][j][2] + bb.x, 0.f);
                float v1y = fmaxf(acc[i][j][3] + bb.y, 0.f);
                if (row0 < NN)
                    ((uint32_t*)hout)[(size_t)row0 * 64 + (col >> 1)] = packbf(v0x, v0y);
                if (row0 + 8 < NN)
                    ((uint32_t*)hout)[(size_t)(row0 + 8) * 64 + (col >> 1)] = packbf(v1x, v1y);
            }
        }
    } else {
        // epilogue: bias + relu + project onto wl2/wr2 (fp32)
        float pp[4][4];
        #pragma unroll
        for (int s = 0; s < 4; s++)
            #pragma unroll
            for (int o = 0; o < 4; o++) pp[s][o] = 0.f;

        #pragma unroll
        for (int j = 0; j < 8; j++) {
            int col = nw * 64 + j * 8 + 2 * t;
            float2 bb = *(const float2*)(bias + col);
            float2 wl2a = *(const float2*)(wl2 + col);
            float2 wl2b = *(const float2*)(wl2 + 128 + col);
            float2 wr2a = *(const float2*)(wr2 + col);
            float2 wr2b = *(const float2*)(wr2 + 128 + col);
            #pragma unroll
            for (int i = 0; i < 2; i++) {
                float vx = fmaxf(acc[i][j][0] + bb.x, 0.f);
                float vy = fmaxf(acc[i][j][1] + bb.y, 0.f);
                pp[2*i][0] += vx * wl2a.x + vy * wl2a.y;
                pp[2*i][1] += vx * wl2b.x + vy * wl2b.y;
                pp[2*i][2] += vx * wr2a.x + vy * wr2a.y;
                pp[2*i][3] += vx * wr2b.x + vy * wr2b.y;
                vx = fmaxf(acc[i][j][2] + bb.x, 0.f);
                vy = fmaxf(acc[i][j][3] + bb.y, 0.f);
                pp[2*i+1][0] += vx * wl2a.x + vy * wl2a.y;
                pp[2*i+1][1] += vx * wl2b.x + vy * wl2b.y;
                pp[2*i+1][2] += vx * wr2a.x + vy * wr2a.y;
                pp[2*i+1][3] += vx * wr2b.x + vy * wr2b.y;
            }
        }
        #pragma unroll
        for (int s = 0; s < 4; s++)
            #pragma unroll
            for (int o = 0; o < 4; o++) {
                pp[s][o] += __shfl_xor_sync(0xffffffffu, pp[s][o], 1);
                pp[s][o] += __shfl_xor_sync(0xffffffffu, pp[s][o], 2);
            }
        float* sred = (float*)sm;   // [128][8]
        if (t == 0) {
            #pragma unroll
            for (int s = 0; s < 4; s++) {
                int lr = mw * 32 + s * 8 + g;
                #pragma unroll
                for (int o = 0; o < 4; o++) sred[lr * 8 + nw * 4 + o] = pp[s][o];
            }
        }
        __syncthreads();
        if (tid < 128) {
            int node = nodeBase + tid;
            if (node < NN) {
                float pl0 = sred[tid * 8 + 0] + sred[tid * 8 + 4];
                float pl1 = sred[tid * 8 + 1] + sred[tid * 8 + 5];
                float pr0 = sred[tid * 8 + 2] + sred[tid * 8 + 6];
                float pr1 = sred[tid * 8 + 3] + sred[tid * 8 + 7];
                *(float2*)&g_pl[node * 2] = make_float2(pl0, pl1);
                *(float2*)&g_pr[node * 2] = make_float2(pr0, pr1);
            }
        }
    }
}

// ---------------- layer 2 aggregation (2-dim) + bias + log_softmax ------------
__global__ void k_final(const float* __restrict__ b2, float* __restrict__ out) {
    int warp = (blockIdx.x * blockDim.x + threadIdx.x) >> 5;
    int lane = threadIdx.x & 31;
    if (warp >= NN) return;
    int s0 = g_row[warp];
    int s1 = g_row[warp + 1];
    float a0 = 0.f, a1 = 0.f;
    for (int e = s0 + lane; e < s1; e += 32) {
        int s = g_csr[e];
        float2 v = *(const float2*)&g_pl[s * 2];
        a0 += v.x;
        a1 += v.y;
    }
    #pragma unroll
    for (int o = 16; o; o >>= 1) {
        a0 += __shfl_xor_sync(0xffffffffu, a0, o);
        a1 += __shfl_xor_sync(0xffffffffu, a1, o);
    }
    if (lane == 0) {
        float inv = g_invdeg[warp];
        float o0 = a0 * inv + b2[0] + g_pr[warp * 2 + 0];
        float o1 = a1 * inv + b2[1] + g_pr[warp * 2 + 1];
        float m = fmaxf(o0, o1);
        float ls = m + logf(expf(o0 - m) + expf(o1 - m));
        out[warp * 2 + 0] = o0 - ls;
        out[warp * 2 + 1] = o1 - ls;
    }
}

// ---------------- launch -----------------------------------------------------
extern "C" void kernel_launch(void* const* d_in, const int* in_sizes, int n_in,
                              void* d_out, int out_size) {
    const float* x    = (const float*)d_in[0];
    const float* wl0  = (const float*)d_in[1];
    const float* b0   = (const float*)d_in[2];
    const float* wr0  = (const float*)d_in[3];
    const float* wl1  = (const float*)d_in[4];
    const float* b1   = (const float*)d_in[5];
    const float* wr1  = (const float*)d_in[6];
    const float* wl2  = (const float*)d_in[7];
    const float* b2   = (const float*)d_in[8];
    const float* wr2  = (const float*)d_in[9];
    const int* esrc   = (const int*)d_in[10];
    const int* edst   = (const int*)d_in[11];
    float* out        = (float*)d_out;

    __nv_bfloat16* xbf;  cudaGetSymbolAddress((void**)&xbf, g_xbf);
    __nv_bfloat16* h1bf; cudaGetSymbolAddress((void**)&h1bf, g_h1bf);
    uint32_t* wp;        cudaGetSymbolAddress((void**)&wp, g_wp);

    const int nblk_scan = (NN + 1023) / 1024;        // 98
    const int layer_smem = (64 * WS2 + 128 * XS2) * (int)sizeof(uint32_t);  // 69632
    cudaFuncSetAttribute(k_layer<0>, cudaFuncAttributeMaxDynamicSharedMemorySize, layer_smem);
    cudaFuncSetAttribute(k_layer<1>, cudaFuncAttributeMaxDynamicSharedMemorySize, layer_smem);

    const int gemm_blocks = (NN + 127) / 128;        // 782
    const int agg_blocks = (NN + 7) / 8;

    // 1: prep (zero counts + cast x + pack weights)
    k_prep<<<XBLK + 128, 256>>>(x, wl0, wr0, wl1, wr1);
    // 2-5: CSR build
    k_hist<<<(EE + 255) / 256, 256>>>(edst);
    k_scan1<<<nblk_scan, 1024>>>();
    k_scan3<<<nblk_scan, 1024>>>();
    k_scatter<<<(EE + 255) / 256, 256>>>(esrc, edst);
    // 6: Layer 0 fused agg+GEMM -> h1 (bf16)
    k_layer<0><<<gemm_blocks, 256, layer_smem>>>(xbf, wp, wp + 8192, b0, h1bf, nullptr, nullptr);
    // 7: Layer 1 fused agg+GEMM + output projection -> g_pl/g_pr
    k_layer<1><<<gemm_blocks, 256, layer_smem>>>(h1bf, wp + 16384, wp + 24576, b1, nullptr, wl2, wr2);
    // 8: Layer 2: 2-dim aggregation + bias + log_softmax
    k_final<<<agg_blocks, 256>>>(b2, out);
}

// round 8
// speedup vs baseline: 1.0040x; 1.0040x over previous
#include <cuda_runtime.h>
#include <cuda_bf16.h>
#include <cstdint>

// Problem constants (fixed by the dataset)
#define NN 100000
#define EE 1600000
#define DH 128

// ---------------- scratch (device globals; no allocation allowed) -------------
__device__ __nv_bfloat16 g_xbf[NN * DH];
__device__ __nv_bfloat16 g_h1bf[NN * DH];
__device__ uint32_t g_wp[4 * 8192];      // 4 matrices, bf16-pair packed [k2][n]
__device__ int   g_counts[NN];
__device__ int   g_row[NN + 1];
__device__ int   g_cursor[NN];
__device__ int   g_csr[EE];
__device__ int   g_bsums[128];
__device__ float g_invdeg[NN];
__device__ float g_pl[NN * 2];
__device__ float g_pr[NN * 2];

__device__ __forceinline__ uint32_t packbf(float a, float b) {
    __nv_bfloat162 h = __floats2bfloat162_rn(a, b);   // .x = a (low), .y = b (high)
    return *reinterpret_cast<uint32_t*>(&h);
}

// ---------------- prep: zero counts + cast x to bf16 + pack weights ----------
#define XBLK 25000   // ceil(NN*64 / 256)

__global__ void k_prep(const float* __restrict__ x,
                       const float* __restrict__ wl0, const float* __restrict__ wr0,
                       const float* __restrict__ wl1, const float* __restrict__ wr1) {
    int gi = blockIdx.x * 256 + threadIdx.x;
    if (blockIdx.x < XBLK) {
        if (gi < NN) g_counts[gi] = 0;
        if (gi < NN * 64) {
            float2 v = ((const float2*)x)[gi];
            reinterpret_cast<uint32_t*>(g_xbf)[gi] = packbf(v.x, v.y);
        }
    } else {
        int i = (blockIdx.x - XBLK) * 256 + threadIdx.x;   // 0..32767
        int m = i >> 13, idx = i & 8191;
        int n = idx & 127, k2 = idx >> 7;
        const float* s = (m == 0) ? wl0 : (m == 1) ? wr0 : (m == 2) ? wl1 : wr1;
        float2 v = *(const float2*)(s + n * 128 + 2 * k2);
        g_wp[m * 8192 + k2 * 128 + n] = packbf(v.x, v.y);
    }
}

// ---------------- CSR build --------------------------------------------------
__global__ void k_hist(const int* __restrict__ dst) {
    int e = blockIdx.x * blockDim.x + threadIdx.x;
    if (e < EE) atomicAdd(&g_counts[dst[e]], 1);
}

__global__ void k_scan1() {
    __shared__ int sd[1024];
    int t = threadIdx.x;
    int g = blockIdx.x * 1024 + t;
    int v = (g < NN) ? g_counts[g] : 0;
    sd[t] = v;
    __syncthreads();
    #pragma unroll
    for (int off = 1; off < 1024; off <<= 1) {
        int x = (t >= off) ? sd[t - off] : 0;
        __syncthreads();
        sd[t] += x;
        __syncthreads();
    }
    if (g < NN) g_row[g] = sd[t] - v;   // exclusive within block
    if (t == 1023) g_bsums[blockIdx.x] = sd[t];
}

// scan of block sums done redundantly per block (98 values, trivial) + finalize
__global__ void k_scan3() {
    __shared__ int sb[128];
    int t = threadIdx.x;
    if (t < 128) sb[t] = (t < 98) ? g_bsums[t] : 0;
    __syncthreads();
    #pragma unroll
    for (int off = 1; off < 128; off <<= 1) {
        int x = (t < 128 && t >= off) ? sb[t - off] : 0;
        __syncthreads();
        if (t < 128) sb[t] += x;
        __syncthreads();
    }
    int myoff = (blockIdx.x == 0) ? 0 : sb[blockIdx.x - 1];   // inclusive -> exclusive
    int g = blockIdx.x * 1024 + t;
    if (g < NN) {
        int r = g_row[g] + myoff;
        g_row[g] = r;
        g_cursor[g] = r;
        int c = g_counts[g];
        g_invdeg[g] = 1.0f / (float)(c > 0 ? c : 1);
    }
    if (blockIdx.x == 0 && t == 0) g_row[NN] = EE;
}

__global__ void k_scatter(const int* __restrict__ src, const int* __restrict__ dst) {
    int e = blockIdx.x * blockDim.x + threadIdx.x;
    if (e < EE) {
        int d = dst[e];
        int pos = atomicAdd(&g_cursor[d], 1);
        g_csr[pos] = src[e];
    }
}

// ---------------- fused layer: bf16 mean-agg + bf16 MMA (+ projection) -------
// out = relu(mean_nbr(hin)@Wl^T + b + hin@Wr^T)
// MODE 0: write 128-dim bf16 result to hout.
// MODE 1: project with wl2/wr2 -> g_pl/g_pr [N,2]; hout untouched.
// Block: M=128 x N=128, 8 warps (4 M x 2 N). K=256 as two K=128 chunks,
// mma m16n8k16 bf16, fp32 accumulate. Gather: 4 batched loads, 2 accumulators.
#define XS2 68    // uint32 (bf16x2) stride: A-frag reads conflict-free
#define WS2 136   // uint32 stride: B-frag reads conflict-free

__device__ __forceinline__ void mma_bf16(float* c, const uint32_t* a, const uint32_t* b) {
    asm volatile(
        "mma.sync.aligned.m16n8k16.row.col.f32.bf16.bf16.f32 "
        "{%0,%1,%2,%3}, {%4,%5,%6,%7}, {%8,%9}, {%0,%1,%2,%3};"
        : "+f"(c[0]), "+f"(c[1]), "+f"(c[2]), "+f"(c[3])
        : "r"(a[0]), "r"(a[1]), "r"(a[2]), "r"(a[3]), "r"(b[0]), "r"(b[1]));
}

__device__ __forceinline__ void addbf(float4& a, uint2 v) {
    float2 f0 = __bfloat1622float2(*(__nv_bfloat162*)&v.x);
    float2 f1 = __bfloat1622float2(*(__nv_bfloat162*)&v.y);
    a.x += f0.x; a.y += f0.y; a.z += f1.x; a.w += f1.y;
}

template <int MODE>
__global__ void __launch_bounds__(256, 2) k_layer(
    const __nv_bfloat16* __restrict__ hin,
    const uint32_t* __restrict__ wpL, const uint32_t* __restrict__ wpR,
    const float* __restrict__ bias, __nv_bfloat16* __restrict__ hout,
    const float* __restrict__ wl2, const float* __restrict__ wr2) {
    extern __shared__ uint32_t sm[];
    uint32_t* sW = sm;                    // [64][WS2]
    uint32_t* sX = sm + 64 * WS2;         // [128][XS2]

    int tid = threadIdx.x;
    int lane = tid & 31, wid = tid >> 5;
    int g = lane >> 2, t = lane & 3;
    int mw = wid & 3, nw = wid >> 2;
    int nodeBase = blockIdx.x * 128;

    float acc[2][8][4];
    #pragma unroll
    for (int i = 0; i < 2; i++)
        #pragma unroll
        for (int j = 0; j < 8; j++)
            #pragma unroll
            for (int q = 0; q < 4; q++) acc[i][j][q] = 0.f;

    #pragma unroll
    for (int chunk = 0; chunk < 2; chunk++) {
        // ---- stage X ----
        if (chunk == 0) {
            // fused mean aggregation: 4 batched loads per iter, 2 accumulators
            const uint2* hin2 = (const uint2*)hin;
            for (int p = 0; p < 16; p++) {
                int r = wid * 16 + p;
                int node = nodeBase + r;
                float4 a0 = make_float4(0.f, 0.f, 0.f, 0.f);
                float4 a1 = a0;
                if (node < NN) {
                    int e = g_row[node], e1 = g_row[node + 1];
                    for (; e + 3 < e1; e += 4) {
                        int sa = g_csr[e],     sb = g_csr[e + 1];
                        int sc = g_csr[e + 2], sd = g_csr[e + 3];
                        uint2 va = __ldg(&hin2[(size_t)sa * 32 + lane]);
                        uint2 vb = __ldg(&hin2[(size_t)sb * 32 + lane]);
                        uint2 vc = __ldg(&hin2[(size_t)sc * 32 + lane]);
                        uint2 vd = __ldg(&hin2[(size_t)sd * 32 + lane]);
                        addbf(a0, va); addbf(a1, vb);
                        addbf(a0, vc); addbf(a1, vd);
                    }
                    if (e + 1 < e1) {
                        uint2 va = __ldg(&hin2[(size_t)g_csr[e] * 32 + lane]);
                        uint2 vb = __ldg(&hin2[(size_t)g_csr[e + 1] * 32 + lane]);
                        addbf(a0, va); addbf(a1, vb);
                        e += 2;
                    }
                    if (e < e1) {
                        uint2 va = __ldg(&hin2[(size_t)g_csr[e] * 32 + lane]);
                        addbf(a0, va);
                    }
                    float sc4 = g_invdeg[node];
                    a0.x = (a0.x + a1.x) * sc4;
                    a0.y = (a0.y + a1.y) * sc4;
                    a0.z = (a0.z + a1.z) * sc4;
                    a0.w = (a0.w + a1.w) * sc4;
                }
                sX[r * XS2 + lane * 2]     = packbf(a0.x, a0.y);
                sX[r * XS2 + lane * 2 + 1] = packbf(a0.z, a0.w);
            }
        } else {
            // root path: coalesced bf16 rows
            for (int i = tid; i < 128 * 64; i += 256) {
                int r = i >> 6, c2 = i & 63;
                int n = nodeBase + r;
                uint32_t v = 0;
                if (n < NN) v = ((const uint32_t*)hin)[(size_t)n * 64 + c2];
                sX[r * XS2 + c2] = v;
            }
        }
        // ---- stage W (pre-packed bf16 pairs, straight copy) ----
        const uint32_t* wp = chunk ? wpR : wpL;
        for (int i = tid; i < 64 * 128; i += 256) {
            int k2 = i >> 7, n = i & 127;
            sW[k2 * WS2 + n] = wp[i];
        }
        __syncthreads();

        #pragma unroll
        for (int ks = 0; ks < 8; ks++) {
            int k02 = ks * 8;   // col2 units (16 k-elements = 8 pairs)
            uint32_t a[2][4], b[8][2];
            #pragma unroll
            for (int i = 0; i < 2; i++) {
                int row = mw * 32 + i * 16 + g;
                a[i][0] = sX[row * XS2 + k02 + t];
                a[i][1] = sX[(row + 8) * XS2 + k02 + t];
                a[i][2] = sX[row * XS2 + k02 + t + 4];
                a[i][3] = sX[(row + 8) * XS2 + k02 + t + 4];
            }
            #pragma unroll
            for (int j = 0; j < 8; j++) {
                int col = nw * 64 + j * 8 + g;
                b[j][0] = sW[(k02 + t) * WS2 + col];
                b[j][1] = sW[(k02 + t + 4) * WS2 + col];
            }
            #pragma unroll
            for (int i = 0; i < 2; i++)
                #pragma unroll
                for (int j = 0; j < 8; j++)
                    mma_bf16(acc[i][j], a[i], b[j]);
        }
        __syncthreads();
    }

    if (MODE == 0) {
        // epilogue: bias + relu -> bf16 hout
        #pragma unroll
        for (int i = 0; i < 2; i++) {
            int row0 = nodeBase + mw * 32 + i * 16 + g;
            #pragma unroll
            for (int j = 0; j < 8; j++) {
                int col = nw * 64 + j * 8 + 2 * t;
                float2 bb = *(const float2*)(bias + col);
                float v0x = fmaxf(acc[i][j][0] + bb.x, 0.f);
                float v0y = fmaxf(acc[i][j][1] + bb.y, 0.f);
                float v1x = fmaxf(acc[i][j][2] + bb.x, 0.f);
                float v1y = fmaxf(acc[i][j][3] + bb.y, 0.f);
                if (row0 < NN)
                    ((uint32_t*)hout)[(size_t)row0 * 64 + (col >> 1)] = packbf(v0x, v0y);
                if (row0 + 8 < NN)
                    ((uint32_t*)hout)[(size_t)(row0 + 8) * 64 + (col >> 1)] = packbf(v1x, v1y);
            }
        }
    } else {
        // epilogue: bias + relu + project onto wl2/wr2 (fp32)
        float pp[4][4];
        #pragma unroll
        for (int s = 0; s < 4; s++)
            #pragma unroll
            for (int o = 0; o < 4; o++) pp[s][o] = 0.f;

        #pragma unroll
        for (int j = 0; j < 8; j++) {
            int col = nw * 64 + j * 8 + 2 * t;
            float2 bb = *(const float2*)(bias + col);
            float2 wl2a = *(const float2*)(wl2 + col);
            float2 wl2b = *(const float2*)(wl2 + 128 + col);
            float2 wr2a = *(const float2*)(wr2 + col);
            float2 wr2b = *(const float2*)(wr2 + 128 + col);
            #pragma unroll
            for (int i = 0; i < 2; i++) {
                float vx = fmaxf(acc[i][j][0] + bb.x, 0.f);
                float vy = fmaxf(acc[i][j][1] + bb.y, 0.f);
                pp[2*i][0] += vx * wl2a.x + vy * wl2a.y;
                pp[2*i][1] += vx * wl2b.x + vy * wl2b.y;
                pp[2*i][2] += vx * wr2a.x + vy * wr2a.y;
                pp[2*i][3] += vx * wr2b.x + vy * wr2b.y;
                vx = fmaxf(acc[i][j][2] + bb.x, 0.f);
                vy = fmaxf(acc[i][j][3] + bb.y, 0.f);
                pp[2*i+1][0] += vx * wl2a.x + vy * wl2a.y;
                pp[2*i+1][1] += vx * wl2b.x + vy * wl2b.y;
                pp[2*i+1][2] += vx * wr2a.x + vy * wr2a.y;
                pp[2*i+1][3] += vx * wr2b.x + vy * wr2b.y;
            }
        }
        #pragma unroll
        for (int s = 0; s < 4; s++)
            #pragma unroll
            for (int o = 0; o < 4; o++) {
                pp[s][o] += __shfl_xor_sync(0xffffffffu, pp[s][o], 1);
                pp[s][o] += __shfl_xor_sync(0xffffffffu, pp[s][o], 2);
            }
        float* sred = (float*)sm;   // [128][8]
        if (t == 0) {
            #pragma unroll
            for (int s = 0; s < 4; s++) {
                int lr = mw * 32 + s * 8 + g;
                #pragma unroll
                for (int o = 0; o < 4; o++) sred[lr * 8 + nw * 4 + o] = pp[s][o];
            }
        }
        __syncthreads();
        if (tid < 128) {
            int node = nodeBase + tid;
            if (node < NN) {
                float pl0 = sred[tid * 8 + 0] + sred[tid * 8 + 4];
                float pl1 = sred[tid * 8 + 1] + sred[tid * 8 + 5];
                float pr0 = sred[tid * 8 + 2] + sred[tid * 8 + 6];
                float pr1 = sred[tid * 8 + 3] + sred[tid * 8 + 7];
                *(float2*)&g_pl[node * 2] = make_float2(pl0, pl1);
                *(float2*)&g_pr[node * 2] = make_float2(pr0, pr1);
            }
        }
    }
}

// ---------------- layer 2 aggregation (2-dim) + bias + log_softmax ------------
__global__ void k_final(const float* __restrict__ b2, float* __restrict__ out) {
    int warp = (blockIdx.x * blockDim.x + threadIdx.x) >> 5;
    int lane = threadIdx.x & 31;
    if (warp >= NN) return;
    int s0 = g_row[warp];
    int s1 = g_row[warp + 1];
    float a0 = 0.f, a1 = 0.f;
    for (int e = s0 + lane; e < s1; e += 32) {
        int s = g_csr[e];
        float2 v = __ldg((const float2*)&g_pl[s * 2]);
        a0 += v.x;
        a1 += v.y;
    }
    #pragma unroll
    for (int o = 16; o; o >>= 1) {
        a0 += __shfl_xor_sync(0xffffffffu, a0, o);
        a1 += __shfl_xor_sync(0xffffffffu, a1, o);
    }
    if (lane == 0) {
        float inv = g_invdeg[warp];
        float o0 = a0 * inv + b2[0] + g_pr[warp * 2 + 0];
        float o1 = a1 * inv + b2[1] + g_pr[warp * 2 + 1];
        float m = fmaxf(o0, o1);
        float ls = m + logf(expf(o0 - m) + expf(o1 - m));
        out[warp * 2 + 0] = o0 - ls;
        out[warp * 2 + 1] = o1 - ls;
    }
}

// ---------------- launch -----------------------------------------------------
extern "C" void kernel_launch(void* const* d_in, const int* in_sizes, int n_in,
                              void* d_out, int out_size) {
    const float* x    = (const float*)d_in[0];
    const float* wl0  = (const float*)d_in[1];
    const float* b0   = (const float*)d_in[2];
    const float* wr0  = (const float*)d_in[3];
    const float* wl1  = (const float*)d_in[4];
    const float* b1   = (const float*)d_in[5];
    const float* wr1  = (const float*)d_in[6];
    const float* wl2  = (const float*)d_in[7];
    const float* b2   = (const float*)d_in[8];
    const float* wr2  = (const float*)d_in[9];
    const int* esrc   = (const int*)d_in[10];
    const int* edst   = (const int*)d_in[11];
    float* out        = (float*)d_out;

    __nv_bfloat16* xbf;  cudaGetSymbolAddress((void**)&xbf, g_xbf);
    __nv_bfloat16* h1bf; cudaGetSymbolAddress((void**)&h1bf, g_h1bf);
    uint32_t* wp;        cudaGetSymbolAddress((void**)&wp, g_wp);

    const int nblk_scan = (NN + 1023) / 1024;        // 98
    const int layer_smem = (64 * WS2 + 128 * XS2) * (int)sizeof(uint32_t);  // 69632
    cudaFuncSetAttribute(k_layer<0>, cudaFuncAttributeMaxDynamicSharedMemorySize, layer_smem);
    cudaFuncSetAttribute(k_layer<1>, cudaFuncAttributeMaxDynamicSharedMemorySize, layer_smem);

    const int gemm_blocks = (NN + 127) / 128;        // 782
    const int agg_blocks = (NN + 7) / 8;

    // 1: prep (zero counts + cast x + pack weights)
    k_prep<<<XBLK + 128, 256>>>(x, wl0, wr0, wl1, wr1);
    // 2-5: CSR build
    k_hist<<<(EE + 255) / 256, 256>>>(edst);
    k_scan1<<<nblk_scan, 1024>>>();
    k_scan3<<<nblk_scan, 1024>>>();
    k_scatter<<<(EE + 255) / 256, 256>>>(esrc, edst);
    // 6: Layer 0 fused agg+GEMM -> h1 (bf16)
    k_layer<0><<<gemm_blocks, 256, layer_smem>>>(xbf, wp, wp + 8192, b0, h1bf, nullptr, nullptr);
    // 7: Layer 1 fused agg+GEMM + output projection -> g_pl/g_pr
    k_layer<1><<<gemm_blocks, 256, layer_smem>>>(h1bf, wp + 16384, wp + 24576, b1, nullptr, wl2, wr2);
    // 8: Layer 2: 2-dim aggregation + bias + log_softmax
    k_final<<<agg_blocks, 256>>>(b2, out);
}

// round 9
// speedup vs baseline: 1.1858x; 1.1812x over previous
#include <cuda_runtime.h>
#include <cuda_bf16.h>
#include <cstdint>

// Problem constants (fixed by the dataset)
#define NN 100000
#define EE 1600000
#define DH 128

// ---------------- scratch (device globals; no allocation allowed) -------------
__device__ __nv_bfloat16 g_xbf[NN * DH];
__device__ __nv_bfloat16 g_h1bf[NN * DH];
__device__ __nv_bfloat16 g_aggbf[NN * DH];
__device__ uint32_t g_wp[4 * 8192];      // 4 matrices, bf16-pair packed [k2][n]
__device__ int   g_counts[NN];
__device__ int   g_row[NN + 1];
__device__ int   g_cursor[NN];
__device__ int   g_csr[EE];
__device__ int   g_bsums[128];
__device__ float g_invdeg[NN];
__device__ float g_pl[NN * 2];
__device__ float g_pr[NN * 2];

__device__ __forceinline__ uint32_t packbf(float a, float b) {
    __nv_bfloat162 h = __floats2bfloat162_rn(a, b);   // .x = a (low), .y = b (high)
    return *reinterpret_cast<uint32_t*>(&h);
}

// ---------------- prep: zero counts + cast x to bf16 + pack weights ----------
#define XBLK 25000   // ceil(NN*64 / 256)

__global__ void k_prep(const float* __restrict__ x,
                       const float* __restrict__ wl0, const float* __restrict__ wr0,
                       const float* __restrict__ wl1, const float* __restrict__ wr1) {
    int gi = blockIdx.x * 256 + threadIdx.x;
    if (blockIdx.x < XBLK) {
        if (gi < NN) g_counts[gi] = 0;
        if (gi < NN * 64) {
            float2 v = ((const float2*)x)[gi];
            reinterpret_cast<uint32_t*>(g_xbf)[gi] = packbf(v.x, v.y);
        }
    } else {
        int i = (blockIdx.x - XBLK) * 256 + threadIdx.x;   // 0..32767
        int m = i >> 13, idx = i & 8191;
        int n = idx & 127, k2 = idx >> 7;
        const float* s = (m == 0) ? wl0 : (m == 1) ? wr0 : (m == 2) ? wl1 : wr1;
        float2 v = *(const float2*)(s + n * 128 + 2 * k2);
        g_wp[m * 8192 + k2 * 128 + n] = packbf(v.x, v.y);
    }
}

// ---------------- CSR build --------------------------------------------------
__global__ void k_hist(const int* __restrict__ dst) {
    int e = blockIdx.x * blockDim.x + threadIdx.x;
    if (e < EE) atomicAdd(&g_counts[dst[e]], 1);
}

__global__ void k_scan1() {
    __shared__ int sd[1024];
    int t = threadIdx.x;
    int g = blockIdx.x * 1024 + t;
    int v = (g < NN) ? g_counts[g] : 0;
    sd[t] = v;
    __syncthreads();
    #pragma unroll
    for (int off = 1; off < 1024; off <<= 1) {
        int x = (t >= off) ? sd[t - off] : 0;
        __syncthreads();
        sd[t] += x;
        __syncthreads();
    }
    if (g < NN) g_row[g] = sd[t] - v;   // exclusive within block
    if (t == 1023) g_bsums[blockIdx.x] = sd[t];
}

// scan of block sums done redundantly per block (98 values, trivial) + finalize
__global__ void k_scan3() {
    __shared__ int sb[128];
    int t = threadIdx.x;
    if (t < 128) sb[t] = (t < 98) ? g_bsums[t] : 0;
    __syncthreads();
    #pragma unroll
    for (int off = 1; off < 128; off <<= 1) {
        int x = (t < 128 && t >= off) ? sb[t - off] : 0;
        __syncthreads();
        if (t < 128) sb[t] += x;
        __syncthreads();
    }
    int myoff = (blockIdx.x == 0) ? 0 : sb[blockIdx.x - 1];   // inclusive -> exclusive
    int g = blockIdx.x * 1024 + t;
    if (g < NN) {
        int r = g_row[g] + myoff;
        g_row[g] = r;
        g_cursor[g] = r;
        int c = g_counts[g];
        g_invdeg[g] = 1.0f / (float)(c > 0 ? c : 1);
    }
    if (blockIdx.x == 0 && t == 0) g_row[NN] = EE;
}

__global__ void k_scatter(const int* __restrict__ src, const int* __restrict__ dst) {
    int e = blockIdx.x * blockDim.x + threadIdx.x;
    if (e < EE) {
        int d = dst[e];
        int pos = atomicAdd(&g_cursor[d], 1);
        g_csr[pos] = src[e];
    }
}

// ---------------- standalone bf16 mean aggregation, warp per node -------------
// Lean register footprint -> high occupancy; 4-way unrolled gather for MLP.
__device__ __forceinline__ void addbf(float4& a, uint2 v) {
    float2 f0 = __bfloat1622float2(*(__nv_bfloat162*)&v.x);
    float2 f1 = __bfloat1622float2(*(__nv_bfloat162*)&v.y);
    a.x += f0.x; a.y += f0.y; a.z += f1.x; a.w += f1.y;
}

__global__ void __launch_bounds__(256) k_aggbf(const __nv_bfloat16* __restrict__ hin,
                                               __nv_bfloat16* __restrict__ aggout) {
    int warp = (blockIdx.x * blockDim.x + threadIdx.x) >> 5;
    int lane = threadIdx.x & 31;
    if (warp >= NN) return;
    const uint2* hin2 = (const uint2*)hin;
    int e = g_row[warp], e1 = g_row[warp + 1];
    float4 a0 = make_float4(0.f, 0.f, 0.f, 0.f);
    float4 a1 = a0, a2 = a0, a3 = a0;
    for (; e + 3 < e1; e += 4) {
        int sa = g_csr[e],     sb = g_csr[e + 1];
        int sc = g_csr[e + 2], sd = g_csr[e + 3];
        uint2 va = hin2[(size_t)sa * 32 + lane];
        uint2 vb = hin2[(size_t)sb * 32 + lane];
        uint2 vc = hin2[(size_t)sc * 32 + lane];
        uint2 vd = hin2[(size_t)sd * 32 + lane];
        addbf(a0, va); addbf(a1, vb); addbf(a2, vc); addbf(a3, vd);
    }
    if (e + 1 < e1) {
        int sa = g_csr[e], sb = g_csr[e + 1];
        uint2 va = hin2[(size_t)sa * 32 + lane];
        uint2 vb = hin2[(size_t)sb * 32 + lane];
        addbf(a0, va); addbf(a1, vb);
        e += 2;
    }
    if (e < e1) {
        uint2 va = hin2[(size_t)g_csr[e] * 32 + lane];
        addbf(a0, va);
    }
    float sc4 = g_invdeg[warp];
    float rx = (a0.x + a1.x + a2.x + a3.x) * sc4;
    float ry = (a0.y + a1.y + a2.y + a3.y) * sc4;
    float rz = (a0.z + a1.z + a2.z + a3.z) * sc4;
    float rw = (a0.w + a1.w + a2.w + a3.w) * sc4;
    uint2 o;
    o.x = packbf(rx, ry);
    o.y = packbf(rz, rw);
    ((uint2*)aggout)[(size_t)warp * 32 + lane] = o;
}

// ---------------- layer: stage + bf16 MMA (+ optional projection) ------------
// out = relu(agg@Wl^T + b + hin@Wr^T)
// MODE 0: write 128-dim bf16 result to hout.
// MODE 1: project with wl2/wr2 -> g_pl/g_pr [N,2]; hout untouched.
// Block: M=128 x N=128, 8 warps (4 M x 2 N). K=256 as two K=128 chunks,
// mma m16n8k16 bf16, fp32 accumulate. Both X stages are coalesced copies.
#define XS2 68    // uint32 (bf16x2) stride: A-frag reads conflict-free
#define WS2 136   // uint32 stride: B-frag reads conflict-free

__device__ __forceinline__ void mma_bf16(float* c, const uint32_t* a, const uint32_t* b) {
    asm volatile(
        "mma.sync.aligned.m16n8k16.row.col.f32.bf16.bf16.f32 "
        "{%0,%1,%2,%3}, {%4,%5,%6,%7}, {%8,%9}, {%0,%1,%2,%3};"
        : "+f"(c[0]), "+f"(c[1]), "+f"(c[2]), "+f"(c[3])
        : "r"(a[0]), "r"(a[1]), "r"(a[2]), "r"(a[3]), "r"(b[0]), "r"(b[1]));
}

template <int MODE>
__global__ void __launch_bounds__(256, 2) k_layer(
    const __nv_bfloat16* __restrict__ agg, const __nv_bfloat16* __restrict__ hin,
    const uint32_t* __restrict__ wpL, const uint32_t* __restrict__ wpR,
    const float* __restrict__ bias, __nv_bfloat16* __restrict__ hout,
    const float* __restrict__ wl2, const float* __restrict__ wr2) {
    extern __shared__ uint32_t sm[];
    uint32_t* sW = sm;                    // [64][WS2]
    uint32_t* sX = sm + 64 * WS2;         // [128][XS2]

    int tid = threadIdx.x;
    int lane = tid & 31, wid = tid >> 5;
    int g = lane >> 2, t = lane & 3;
    int mw = wid & 3, nw = wid >> 2;
    int nodeBase = blockIdx.x * 128;

    float acc[2][8][4];
    #pragma unroll
    for (int i = 0; i < 2; i++)
        #pragma unroll
        for (int j = 0; j < 8; j++)
            #pragma unroll
            for (int q = 0; q < 4; q++) acc[i][j][q] = 0.f;

    #pragma unroll
    for (int chunk = 0; chunk < 2; chunk++) {
        // ---- stage X: coalesced bf16 rows (agg for chunk 0, root for chunk 1) --
        const uint32_t* xsrc = (const uint32_t*)(chunk ? hin : agg);
        for (int i = tid; i < 128 * 64; i += 256) {
            int r = i >> 6, c2 = i & 63;
            int n = nodeBase + r;
            uint32_t v = 0;
            if (n < NN) v = xsrc[(size_t)n * 64 + c2];
            sX[r * XS2 + c2] = v;
        }
        // ---- stage W (pre-packed bf16 pairs, straight copy) ----
        const uint32_t* wp = chunk ? wpR : wpL;
        for (int i = tid; i < 64 * 128; i += 256) {
            int k2 = i >> 7, n = i & 127;
            sW[k2 * WS2 + n] = wp[i];
        }
        __syncthreads();

        #pragma unroll
        for (int ks = 0; ks < 8; ks++) {
            int k02 = ks * 8;   // col2 units (16 k-elements = 8 pairs)
            uint32_t a[2][4], b[8][2];
            #pragma unroll
            for (int i = 0; i < 2; i++) {
                int row = mw * 32 + i * 16 + g;
                a[i][0] = sX[row * XS2 + k02 + t];
                a[i][1] = sX[(row + 8) * XS2 + k02 + t];
                a[i][2] = sX[row * XS2 + k02 + t + 4];
                a[i][3] = sX[(row + 8) * XS2 + k02 + t + 4];
            }
            #pragma unroll
            for (int j = 0; j < 8; j++) {
                int col = nw * 64 + j * 8 + g;
                b[j][0] = sW[(k02 + t) * WS2 + col];
                b[j][1] = sW[(k02 + t + 4) * WS2 + col];
            }
            #pragma unroll
            for (int i = 0; i < 2; i++)
                #pragma unroll
                for (int j = 0; j < 8; j++)
                    mma_bf16(acc[i][j], a[i], b[j]);
        }
        __syncthreads();
    }

    if (MODE == 0) {
        // epilogue: bias + relu -> bf16 hout
        #pragma unroll
        for (int i = 0; i < 2; i++) {
            int row0 = nodeBase + mw * 32 + i * 16 + g;
            #pragma unroll
            for (int j = 0; j < 8; j++) {
                int col = nw * 64 + j * 8 + 2 * t;
                float2 bb = *(const float2*)(bias + col);
                float v0x = fmaxf(acc[i][j][0] + bb.x, 0.f);
                float v0y = fmaxf(acc[i][j][1] + bb.y, 0.f);
                float v1x = fmaxf(acc[i][j][2] + bb.x, 0.f);
                float v1y = fmaxf(acc[i][j][3] + bb.y, 0.f);
                if (row0 < NN)
                    ((uint32_t*)hout)[(size_t)row0 * 64 + (col >> 1)] = packbf(v0x, v0y);
                if (row0 + 8 < NN)
                    ((uint32_t*)hout)[(size_t)(row0 + 8) * 64 + (col >> 1)] = packbf(v1x, v1y);
            }
        }
    } else {
        // epilogue: bias + relu + project onto wl2/wr2 (fp32)
        float pp[4][4];
        #pragma unroll
        for (int s = 0; s < 4; s++)
            #pragma unroll
            for (int o = 0; o < 4; o++) pp[s][o] = 0.f;

        #pragma unroll
        for (int j = 0; j < 8; j++) {
            int col = nw * 64 + j * 8 + 2 * t;
            float2 bb = *(const float2*)(bias + col);
            float2 wl2a = *(const float2*)(wl2 + col);
            float2 wl2b = *(const float2*)(wl2 + 128 + col);
            float2 wr2a = *(const float2*)(wr2 + col);
            float2 wr2b = *(const float2*)(wr2 + 128 + col);
            #pragma unroll
            for (int i = 0; i < 2; i++) {
                float vx = fmaxf(acc[i][j][0] + bb.x, 0.f);
                float vy = fmaxf(acc[i][j][1] + bb.y, 0.f);
                pp[2*i][0] += vx * wl2a.x + vy * wl2a.y;
                pp[2*i][1] += vx * wl2b.x + vy * wl2b.y;
                pp[2*i][2] += vx * wr2a.x + vy * wr2a.y;
                pp[2*i][3] += vx * wr2b.x + vy * wr2b.y;
                vx = fmaxf(acc[i][j][2] + bb.x, 0.f);
                vy = fmaxf(acc[i][j][3] + bb.y, 0.f);
                pp[2*i+1][0] += vx * wl2a.x + vy * wl2a.y;
                pp[2*i+1][1] += vx * wl2b.x + vy * wl2b.y;
                pp[2*i+1][2] += vx * wr2a.x + vy * wr2a.y;
                pp[2*i+1][3] += vx * wr2b.x + vy * wr2b.y;
            }
        }
        #pragma unroll
        for (int s = 0; s < 4; s++)
            #pragma unroll
            for (int o = 0; o < 4; o++) {
                pp[s][o] += __shfl_xor_sync(0xffffffffu, pp[s][o], 1);
                pp[s][o] += __shfl_xor_sync(0xffffffffu, pp[s][o], 2);
            }
        float* sred = (float*)sm;   // [128][8]
        if (t == 0) {
            #pragma unroll
            for (int s = 0; s < 4; s++) {
                int lr = mw * 32 + s * 8 + g;
                #pragma unroll
                for (int o = 0; o < 4; o++) sred[lr * 8 + nw * 4 + o] = pp[s][o];
            }
        }
        __syncthreads();
        if (tid < 128) {
            int node = nodeBase + tid;
            if (node < NN) {
                float pl0 = sred[tid * 8 + 0] + sred[tid * 8 + 4];
                float pl1 = sred[tid * 8 + 1] + sred[tid * 8 + 5];
                float pr0 = sred[tid * 8 + 2] + sred[tid * 8 + 6];
                float pr1 = sred[tid * 8 + 3] + sred[tid * 8 + 7];
                *(float2*)&g_pl[node * 2] = make_float2(pl0, pl1);
                *(float2*)&g_pr[node * 2] = make_float2(pr0, pr1);
            }
        }
    }
}

// ---------------- layer 2 aggregation (2-dim) + bias + log_softmax ------------
__global__ void k_final(const float* __restrict__ b2, float* __restrict__ out) {
    int warp = (blockIdx.x * blockDim.x + threadIdx.x) >> 5;
    int lane = threadIdx.x & 31;
    if (warp >= NN) return;
    int s0 = g_row[warp];
    int s1 = g_row[warp + 1];
    float a0 = 0.f, a1 = 0.f;
    for (int e = s0 + lane; e < s1; e += 32) {
        int s = g_csr[e];
        float2 v = *(const float2*)&g_pl[s * 2];
        a0 += v.x;
        a1 += v.y;
    }
    #pragma unroll
    for (int o = 16; o; o >>= 1) {
        a0 += __shfl_xor_sync(0xffffffffu, a0, o);
        a1 += __shfl_xor_sync(0xffffffffu, a1, o);
    }
    if (lane == 0) {
        float inv = g_invdeg[warp];
        float o0 = a0 * inv + b2[0] + g_pr[warp * 2 + 0];
        float o1 = a1 * inv + b2[1] + g_pr[warp * 2 + 1];
        float m = fmaxf(o0, o1);
        float ls = m + logf(expf(o0 - m) + expf(o1 - m));
        out[warp * 2 + 0] = o0 - ls;
        out[warp * 2 + 1] = o1 - ls;
    }
}

// ---------------- launch -----------------------------------------------------
extern "C" void kernel_launch(void* const* d_in, const int* in_sizes, int n_in,
                              void* d_out, int out_size) {
    const float* x    = (const float*)d_in[0];
    const float* wl0  = (const float*)d_in[1];
    const float* b0   = (const float*)d_in[2];
    const float* wr0  = (const float*)d_in[3];
    const float* wl1  = (const float*)d_in[4];
    const float* b1   = (const float*)d_in[5];
    const float* wr1  = (const float*)d_in[6];
    const float* wl2  = (const float*)d_in[7];
    const float* b2   = (const float*)d_in[8];
    const float* wr2  = (const float*)d_in[9];
    const int* esrc   = (const int*)d_in[10];
    const int* edst   = (const int*)d_in[11];
    float* out        = (float*)d_out;

    __nv_bfloat16* xbf;   cudaGetSymbolAddress((void**)&xbf, g_xbf);
    __nv_bfloat16* h1bf;  cudaGetSymbolAddress((void**)&h1bf, g_h1bf);
    __nv_bfloat16* aggbf; cudaGetSymbolAddress((void**)&aggbf, g_aggbf);
    uint32_t* wp;         cudaGetSymbolAddress((void**)&wp, g_wp);

    const int nblk_scan = (NN + 1023) / 1024;        // 98
    const int layer_smem = (64 * WS2 + 128 * XS2) * (int)sizeof(uint32_t);  // 69632
    cudaFuncSetAttribute(k_layer<0>, cudaFuncAttributeMaxDynamicSharedMemorySize, layer_smem);
    cudaFuncSetAttribute(k_layer<1>, cudaFuncAttributeMaxDynamicSharedMemorySize, layer_smem);

    const int gemm_blocks = (NN + 127) / 128;        // 782
    const int agg_blocks = (NN + 7) / 8;             // warp per node

    // 1: prep (zero counts + cast x + pack weights)
    k_prep<<<XBLK + 128, 256>>>(x, wl0, wr0, wl1, wr1);
    // 2-5: CSR build
    k_hist<<<(EE + 255) / 256, 256>>>(edst);
    k_scan1<<<nblk_scan, 1024>>>();
    k_scan3<<<nblk_scan, 1024>>>();
    k_scatter<<<(EE + 255) / 256, 256>>>(esrc, edst);
    // 6: Layer 0 aggregation (high occupancy, MLP=4)
    k_aggbf<<<agg_blocks, 256>>>(xbf, aggbf);
    // 7: Layer 0 stage+MMA -> h1 (bf16)
    k_layer<0><<<gemm_blocks, 256, layer_smem>>>(aggbf, xbf, wp, wp + 8192, b0, h1bf, nullptr, nullptr);
    // 8: Layer 1 aggregation
    k_aggbf<<<agg_blocks, 256>>>(h1bf, aggbf);
    // 9: Layer 1 stage+MMA + output projection -> g_pl/g_pr
    k_layer<1><<<gemm_blocks, 256, layer_smem>>>(aggbf, h1bf, wp + 16384, wp + 24576, b1, nullptr, wl2, wr2);
    // 10: Layer 2: 2-dim aggregation + bias + log_softmax
    k_final<<<agg_blocks, 256>>>(b2, out);
}

// round 10
// speedup vs baseline: 1.2202x; 1.0290x over previous
#include <cuda_runtime.h>
#include <cuda_bf16.h>
#include <cstdint>

// Problem constants (fixed by the dataset)
#define NN 100000
#define EE 1600000
#define DH 128

// ---------------- scratch (device globals; no allocation allowed) -------------
__device__ __nv_bfloat16 g_xbf[NN * DH];
__device__ __nv_bfloat16 g_h1bf[NN * DH];
__device__ __nv_bfloat16 g_aggbf[NN * DH];
__device__ uint32_t g_wp[4 * 8192];      // 4 matrices, bf16-pair packed [k2][n]
__device__ int   g_counts[NN];
__device__ int   g_row[NN + 1];
__device__ int   g_cursor[NN];
__device__ int   g_csr[EE];
__device__ int   g_bsums[128];
__device__ float g_invdeg[NN];
__device__ float g_pl[NN * 2];
__device__ float g_pr[NN * 2];

__device__ __forceinline__ uint32_t packbf(float a, float b) {
    __nv_bfloat162 h = __floats2bfloat162_rn(a, b);   // .x = a (low), .y = b (high)
    return *reinterpret_cast<uint32_t*>(&h);
}

// ---------------- prep: zero counts + cast x to bf16 + pack weights ----------
#define XBLK 25000   // ceil(NN*64 / 256)

__global__ void k_prep(const float* __restrict__ x,
                       const float* __restrict__ wl0, const float* __restrict__ wr0,
                       const float* __restrict__ wl1, const float* __restrict__ wr1) {
    int gi = blockIdx.x * 256 + threadIdx.x;
    if (blockIdx.x < XBLK) {
        if (gi < NN) g_counts[gi] = 0;
        if (gi < NN * 64) {
            float2 v = ((const float2*)x)[gi];
            reinterpret_cast<uint32_t*>(g_xbf)[gi] = packbf(v.x, v.y);
        }
    } else {
        int i = (blockIdx.x - XBLK) * 256 + threadIdx.x;   // 0..32767
        int m = i >> 13, idx = i & 8191;
        int n = idx & 127, k2 = idx >> 7;
        const float* s = (m == 0) ? wl0 : (m == 1) ? wr0 : (m == 2) ? wl1 : wr1;
        float2 v = *(const float2*)(s + n * 128 + 2 * k2);
        g_wp[m * 8192 + k2 * 128 + n] = packbf(v.x, v.y);
    }
}

// ---------------- CSR build --------------------------------------------------
__global__ void k_hist(const int* __restrict__ dst) {
    int e = blockIdx.x * blockDim.x + threadIdx.x;
    if (e < EE) atomicAdd(&g_counts[dst[e]], 1);
}

__global__ void k_scan1() {
    __shared__ int sd[1024];
    int t = threadIdx.x;
    int g = blockIdx.x * 1024 + t;
    int v = (g < NN) ? g_counts[g] : 0;
    sd[t] = v;
    __syncthreads();
    #pragma unroll
    for (int off = 1; off < 1024; off <<= 1) {
        int x = (t >= off) ? sd[t - off] : 0;
        __syncthreads();
        sd[t] += x;
        __syncthreads();
    }
    if (g < NN) g_row[g] = sd[t] - v;   // exclusive within block
    if (t == 1023) g_bsums[blockIdx.x] = sd[t];
}

// scan of block sums done redundantly per block (98 values, trivial) + finalize
__global__ void k_scan3() {
    __shared__ int sb[128];
    int t = threadIdx.x;
    if (t < 128) sb[t] = (t < 98) ? g_bsums[t] : 0;
    __syncthreads();
    #pragma unroll
    for (int off = 1; off < 128; off <<= 1) {
        int x = (t < 128 && t >= off) ? sb[t - off] : 0;
        __syncthreads();
        if (t < 128) sb[t] += x;
        __syncthreads();
    }
    int myoff = (blockIdx.x == 0) ? 0 : sb[blockIdx.x - 1];   // inclusive -> exclusive
    int g = blockIdx.x * 1024 + t;
    if (g < NN) {
        int r = g_row[g] + myoff;
        g_row[g] = r;
        g_cursor[g] = r;
        int c = g_counts[g];
        g_invdeg[g] = 1.0f / (float)(c > 0 ? c : 1);
    }
    if (blockIdx.x == 0 && t == 0) g_row[NN] = EE;
}

__global__ void k_scatter(const int* __restrict__ src, const int* __restrict__ dst) {
    int e = blockIdx.x * blockDim.x + threadIdx.x;
    if (e < EE) {
        int d = dst[e];
        int pos = atomicAdd(&g_cursor[d], 1);
        g_csr[pos] = src[e];
    }
}

// ---------------- standalone bf16 mean aggregation, warp per node -------------
// Lean register footprint -> deep unroll is affordable; 8 batched loads/iter.
__device__ __forceinline__ void addbf(float4& a, uint2 v) {
    float2 f0 = __bfloat1622float2(*(__nv_bfloat162*)&v.x);
    float2 f1 = __bfloat1622float2(*(__nv_bfloat162*)&v.y);
    a.x += f0.x; a.y += f0.y; a.z += f1.x; a.w += f1.y;
}

__global__ void __launch_bounds__(256) k_aggbf(const __nv_bfloat16* __restrict__ hin,
                                               __nv_bfloat16* __restrict__ aggout) {
    int warp = (blockIdx.x * blockDim.x + threadIdx.x) >> 5;
    int lane = threadIdx.x & 31;
    if (warp >= NN) return;
    const uint2* hin2 = (const uint2*)hin;
    int e = g_row[warp], e1 = g_row[warp + 1];
    float4 a0 = make_float4(0.f, 0.f, 0.f, 0.f);
    float4 a1 = a0, a2 = a0, a3 = a0;
    // 8-way batched loads (MLP=8), 4 accumulators
    for (; e + 7 < e1; e += 8) {
        int i0 = g_csr[e],     i1 = g_csr[e + 1];
        int i2 = g_csr[e + 2], i3 = g_csr[e + 3];
        int i4 = g_csr[e + 4], i5 = g_csr[e + 5];
        int i6 = g_csr[e + 6], i7 = g_csr[e + 7];
        uint2 v0 = hin2[(size_t)i0 * 32 + lane];
        uint2 v1 = hin2[(size_t)i1 * 32 + lane];
        uint2 v2 = hin2[(size_t)i2 * 32 + lane];
        uint2 v3 = hin2[(size_t)i3 * 32 + lane];
        uint2 v4 = hin2[(size_t)i4 * 32 + lane];
        uint2 v5 = hin2[(size_t)i5 * 32 + lane];
        uint2 v6 = hin2[(size_t)i6 * 32 + lane];
        uint2 v7 = hin2[(size_t)i7 * 32 + lane];
        addbf(a0, v0); addbf(a1, v1); addbf(a2, v2); addbf(a3, v3);
        addbf(a0, v4); addbf(a1, v5); addbf(a2, v6); addbf(a3, v7);
    }
    if (e + 3 < e1) {
        int i0 = g_csr[e],     i1 = g_csr[e + 1];
        int i2 = g_csr[e + 2], i3 = g_csr[e + 3];
        uint2 v0 = hin2[(size_t)i0 * 32 + lane];
        uint2 v1 = hin2[(size_t)i1 * 32 + lane];
        uint2 v2 = hin2[(size_t)i2 * 32 + lane];
        uint2 v3 = hin2[(size_t)i3 * 32 + lane];
        addbf(a0, v0); addbf(a1, v1); addbf(a2, v2); addbf(a3, v3);
        e += 4;
    }
    if (e + 1 < e1) {
        uint2 v0 = hin2[(size_t)g_csr[e] * 32 + lane];
        uint2 v1 = hin2[(size_t)g_csr[e + 1] * 32 + lane];
        addbf(a0, v0); addbf(a1, v1);
        e += 2;
    }
    if (e < e1) {
        uint2 v0 = hin2[(size_t)g_csr[e] * 32 + lane];
        addbf(a0, v0);
    }
    float sc4 = g_invdeg[warp];
    float rx = (a0.x + a1.x + a2.x + a3.x) * sc4;
    float ry = (a0.y + a1.y + a2.y + a3.y) * sc4;
    float rz = (a0.z + a1.z + a2.z + a3.z) * sc4;
    float rw = (a0.w + a1.w + a2.w + a3.w) * sc4;
    uint2 o;
    o.x = packbf(rx, ry);
    o.y = packbf(rz, rw);
    ((uint2*)aggout)[(size_t)warp * 32 + lane] = o;
}

// ---------------- layer: stage + bf16 MMA (+ optional projection) ------------
// out = relu(agg@Wl^T + b + hin@Wr^T)
// MODE 0: write 128-dim bf16 result to hout.
// MODE 1: project with wl2/wr2 -> g_pl/g_pr [N,2]; hout untouched.
#define XS2 68    // uint32 (bf16x2) stride: A-frag reads conflict-free
#define WS2 136   // uint32 stride: B-frag reads conflict-free

__device__ __forceinline__ void mma_bf16(float* c, const uint32_t* a, const uint32_t* b) {
    asm volatile(
        "mma.sync.aligned.m16n8k16.row.col.f32.bf16.bf16.f32 "
        "{%0,%1,%2,%3}, {%4,%5,%6,%7}, {%8,%9}, {%0,%1,%2,%3};"
        : "+f"(c[0]), "+f"(c[1]), "+f"(c[2]), "+f"(c[3])
        : "r"(a[0]), "r"(a[1]), "r"(a[2]), "r"(a[3]), "r"(b[0]), "r"(b[1]));
}

template <int MODE>
__global__ void __launch_bounds__(256, 2) k_layer(
    const __nv_bfloat16* __restrict__ agg, const __nv_bfloat16* __restrict__ hin,
    const uint32_t* __restrict__ wpL, const uint32_t* __restrict__ wpR,
    const float* __restrict__ bias, __nv_bfloat16* __restrict__ hout,
    const float* __restrict__ wl2, const float* __restrict__ wr2) {
    extern __shared__ uint32_t sm[];
    uint32_t* sW = sm;                    // [64][WS2]
    uint32_t* sX = sm + 64 * WS2;         // [128][XS2]

    int tid = threadIdx.x;
    int lane = tid & 31, wid = tid >> 5;
    int g = lane >> 2, t = lane & 3;
    int mw = wid & 3, nw = wid >> 2;
    int nodeBase = blockIdx.x * 128;

    float acc[2][8][4];
    #pragma unroll
    for (int i = 0; i < 2; i++)
        #pragma unroll
        for (int j = 0; j < 8; j++)
            #pragma unroll
            for (int q = 0; q < 4; q++) acc[i][j][q] = 0.f;

    #pragma unroll
    for (int chunk = 0; chunk < 2; chunk++) {
        // ---- stage X: coalesced bf16 rows (agg for chunk 0, root for chunk 1) --
        const uint32_t* xsrc = (const uint32_t*)(chunk ? hin : agg);
        for (int i = tid; i < 128 * 64; i += 256) {
            int r = i >> 6, c2 = i & 63;
            int n = nodeBase + r;
            uint32_t v = 0;
            if (n < NN) v = xsrc[(size_t)n * 64 + c2];
            sX[r * XS2 + c2] = v;
        }
        // ---- stage W (pre-packed bf16 pairs, straight copy) ----
        const uint32_t* wp = chunk ? wpR : wpL;
        for (int i = tid; i < 64 * 128; i += 256) {
            int k2 = i >> 7, n = i & 127;
            sW[k2 * WS2 + n] = wp[i];
        }
        __syncthreads();

        #pragma unroll
        for (int ks = 0; ks < 8; ks++) {
            int k02 = ks * 8;   // col2 units (16 k-elements = 8 pairs)
            uint32_t a[2][4], b[8][2];
            #pragma unroll
            for (int i = 0; i < 2; i++) {
                int row = mw * 32 + i * 16 + g;
                a[i][0] = sX[row * XS2 + k02 + t];
                a[i][1] = sX[(row + 8) * XS2 + k02 + t];
                a[i][2] = sX[row * XS2 + k02 + t + 4];
                a[i][3] = sX[(row + 8) * XS2 + k02 + t + 4];
            }
            #pragma unroll
            for (int j = 0; j < 8; j++) {
                int col = nw * 64 + j * 8 + g;
                b[j][0] = sW[(k02 + t) * WS2 + col];
                b[j][1] = sW[(k02 + t + 4) * WS2 + col];
            }
            #pragma unroll
            for (int i = 0; i < 2; i++)
                #pragma unroll
                for (int j = 0; j < 8; j++)
                    mma_bf16(acc[i][j], a[i], b[j]);
        }
        __syncthreads();
    }

    if (MODE == 0) {
        // epilogue: bias + relu -> bf16 hout
        #pragma unroll
        for (int i = 0; i < 2; i++) {
            int row0 = nodeBase + mw * 32 + i * 16 + g;
            #pragma unroll
            for (int j = 0; j < 8; j++) {
                int col = nw * 64 + j * 8 + 2 * t;
                float2 bb = *(const float2*)(bias + col);
                float v0x = fmaxf(acc[i][j][0] + bb.x, 0.f);
                float v0y = fmaxf(acc[i][j][1] + bb.y, 0.f);
                float v1x = fmaxf(acc[i][j][2] + bb.x, 0.f);
                float v1y = fmaxf(acc[i][j][3] + bb.y, 0.f);
                if (row0 < NN)
                    ((uint32_t*)hout)[(size_t)row0 * 64 + (col >> 1)] = packbf(v0x, v0y);
                if (row0 + 8 < NN)
                    ((uint32_t*)hout)[(size_t)(row0 + 8) * 64 + (col >> 1)] = packbf(v1x, v1y);
            }
        }
    } else {
        // epilogue: bias + relu + project onto wl2/wr2 (fp32)
        float pp[4][4];
        #pragma unroll
        for (int s = 0; s < 4; s++)
            #pragma unroll
            for (int o = 0; o < 4; o++) pp[s][o] = 0.f;

        #pragma unroll
        for (int j = 0; j < 8; j++) {
            int col = nw * 64 + j * 8 + 2 * t;
            float2 bb = *(const float2*)(bias + col);
            float2 wl2a = *(const float2*)(wl2 + col);
            float2 wl2b = *(const float2*)(wl2 + 128 + col);
            float2 wr2a = *(const float2*)(wr2 + col);
            float2 wr2b = *(const float2*)(wr2 + 128 + col);
            #pragma unroll
            for (int i = 0; i < 2; i++) {
                float vx = fmaxf(acc[i][j][0] + bb.x, 0.f);
                float vy = fmaxf(acc[i][j][1] + bb.y, 0.f);
                pp[2*i][0] += vx * wl2a.x + vy * wl2a.y;
                pp[2*i][1] += vx * wl2b.x + vy * wl2b.y;
                pp[2*i][2] += vx * wr2a.x + vy * wr2a.y;
                pp[2*i][3] += vx * wr2b.x + vy * wr2b.y;
                vx = fmaxf(acc[i][j][2] + bb.x, 0.f);
                vy = fmaxf(acc[i][j][3] + bb.y, 0.f);
                pp[2*i+1][0] += vx * wl2a.x + vy * wl2a.y;
                pp[2*i+1][1] += vx * wl2b.x + vy * wl2b.y;
                pp[2*i+1][2] += vx * wr2a.x + vy * wr2a.y;
                pp[2*i+1][3] += vx * wr2b.x + vy * wr2b.y;
            }
        }
        #pragma unroll
        for (int s = 0; s < 4; s++)
            #pragma unroll
            for (int o = 0; o < 4; o++) {
                pp[s][o] += __shfl_xor_sync(0xffffffffu, pp[s][o], 1);
                pp[s][o] += __shfl_xor_sync(0xffffffffu, pp[s][o], 2);
            }
        float* sred = (float*)sm;   // [128][8]
        if (t == 0) {
            #pragma unroll
            for (int s = 0; s < 4; s++) {
                int lr = mw * 32 + s * 8 + g;
                #pragma unroll
                for (int o = 0; o < 4; o++) sred[lr * 8 + nw * 4 + o] = pp[s][o];
            }
        }
        __syncthreads();
        if (tid < 128) {
            int node = nodeBase + tid;
            if (node < NN) {
                float pl0 = sred[tid * 8 + 0] + sred[tid * 8 + 4];
                float pl1 = sred[tid * 8 + 1] + sred[tid * 8 + 5];
                float pr0 = sred[tid * 8 + 2] + sred[tid * 8 + 6];
                float pr1 = sred[tid * 8 + 3] + sred[tid * 8 + 7];
                *(float2*)&g_pl[node * 2] = make_float2(pl0, pl1);
                *(float2*)&g_pr[node * 2] = make_float2(pr0, pr1);
            }
        }
    }
}

// ---------------- layer 2 aggregation (2-dim) + bias + log_softmax ------------
__global__ void k_final(const float* __restrict__ b2, float* __restrict__ out) {
    int warp = (blockIdx.x * blockDim.x + threadIdx.x) >> 5;
    int lane = threadIdx.x & 31;
    if (warp >= NN) return;
    int s0 = g_row[warp];
    int s1 = g_row[warp + 1];
    float a0 = 0.f, a1 = 0.f;
    for (int e = s0 + lane; e < s1; e += 32) {
        int s = g_csr[e];
        float2 v = *(const float2*)&g_pl[s * 2];
        a0 += v.x;
        a1 += v.y;
    }
    #pragma unroll
    for (int o = 16; o; o >>= 1) {
        a0 += __shfl_xor_sync(0xffffffffu, a0, o);
        a1 += __shfl_xor_sync(0xffffffffu, a1, o);
    }
    if (lane == 0) {
        float inv = g_invdeg[warp];
        float o0 = a0 * inv + b2[0] + g_pr[warp * 2 + 0];
        float o1 = a1 * inv + b2[1] + g_pr[warp * 2 + 1];
        float m = fmaxf(o0, o1);
        float ls = m + logf(expf(o0 - m) + expf(o1 - m));
        out[warp * 2 + 0] = o0 - ls;
        out[warp * 2 + 1] = o1 - ls;
    }
}

// ---------------- launch -----------------------------------------------------
extern "C" void kernel_launch(void* const* d_in, const int* in_sizes, int n_in,
                              void* d_out, int out_size) {
    const float* x    = (const float*)d_in[0];
    const float* wl0  = (const float*)d_in[1];
    const float* b0   = (const float*)d_in[2];
    const float* wr0  = (const float*)d_in[3];
    const float* wl1  = (const float*)d_in[4];
    const float* b1   = (const float*)d_in[5];
    const float* wr1  = (const float*)d_in[6];
    const float* wl2  = (const float*)d_in[7];
    const float* b2   = (const float*)d_in[8];
    const float* wr2  = (const float*)d_in[9];
    const int* esrc   = (const int*)d_in[10];
    const int* edst   = (const int*)d_in[11];
    float* out        = (float*)d_out;

    __nv_bfloat16* xbf;   cudaGetSymbolAddress((void**)&xbf, g_xbf);
    __nv_bfloat16* h1bf;  cudaGetSymbolAddress((void**)&h1bf, g_h1bf);
    __nv_bfloat16* aggbf; cudaGetSymbolAddress((void**)&aggbf, g_aggbf);
    uint32_t* wp;         cudaGetSymbolAddress((void**)&wp, g_wp);

    const int nblk_scan = (NN + 1023) / 1024;        // 98
    const int layer_smem = (64 * WS2 + 128 * XS2) * (int)sizeof(uint32_t);  // 69632
    cudaFuncSetAttribute(k_layer<0>, cudaFuncAttributeMaxDynamicSharedMemorySize, layer_smem);
    cudaFuncSetAttribute(k_layer<1>, cudaFuncAttributeMaxDynamicSharedMemorySize, layer_smem);

    const int gemm_blocks = (NN + 127) / 128;        // 782
    const int agg_blocks = (NN + 7) / 8;             // warp per node

    // 1: prep (zero counts + cast x + pack weights)
    k_prep<<<XBLK + 128, 256>>>(x, wl0, wr0, wl1, wr1);
    // 2-5: CSR build
    k_hist<<<(EE + 255) / 256, 256>>>(edst);
    k_scan1<<<nblk_scan, 1024>>>();
    k_scan3<<<nblk_scan, 1024>>>();
    k_scatter<<<(EE + 255) / 256, 256>>>(esrc, edst);
    // 6: Layer 0 aggregation (high occupancy, MLP=8)
    k_aggbf<<<agg_blocks, 256>>>(xbf, aggbf);
    // 7: Layer 0 stage+MMA -> h1 (bf16)
    k_layer<0><<<gemm_blocks, 256, layer_smem>>>(aggbf, xbf, wp, wp + 8192, b0, h1bf, nullptr, nullptr);
    // 8: Layer 1 aggregation
    k_aggbf<<<agg_blocks, 256>>>(h1bf, aggbf);
    // 9: Layer 1 stage+MMA + output projection -> g_pl/g_pr
    k_layer<1><<<gemm_blocks, 256, layer_smem>>>(aggbf, h1bf, wp + 16384, wp + 24576, b1, nullptr, wl2, wr2);
    // 10: Layer 2: 2-dim aggregation + bias + log_softmax
    k_final<<<agg_blocks, 256>>>(b2, out);
}

// round 13
// speedup vs baseline: 1.3630x; 1.1170x over previous
#include <cuda_runtime.h>
#include <cuda_bf16.h>
#include <cstdint>

// Problem constants (fixed by the dataset)
#define NN 100000
#define EE 1600000
#define DH 128

// ---------------- scratch (device globals; no allocation allowed) -------------
__device__ __nv_bfloat16 g_xbf[NN * DH];
__device__ __nv_bfloat16 g_h1bf[NN * DH];
__device__ __nv_bfloat16 g_aggbf[NN * DH];
__device__ uint32_t g_wp[4 * 8192];      // 4 matrices, bf16-pair packed [k2][n]
__device__ int   g_counts[NN];
__device__ int   g_row[NN + 1];
__device__ int   g_cursor[NN];
__device__ int   g_csr[EE];
__device__ int   g_bsums[128];
__device__ float g_invdeg[NN];
__device__ float g_pl[NN * 2];
__device__ float g_pr[NN * 2];

__device__ __forceinline__ uint32_t packbf(float a, float b) {
    __nv_bfloat162 h = __floats2bfloat162_rn(a, b);   // .x = a (low), .y = b (high)
    return *reinterpret_cast<uint32_t*>(&h);
}

// ---------------- zero counts -------------------------------------------------
__global__ void k_zero() {
    int i = blockIdx.x * 1024 + threadIdx.x;
    if (i < NN) g_counts[i] = 0;
}

// ---------------- merged prep: cast x + pack weights + histogram --------------
#define CAST_ITEMS (NN * 64)                 // 6,400,000 float2 -> bf16x2
#define PREP_TOTAL (CAST_ITEMS + EE + 32768) // + hist + weight-pack

__global__ void k_prep2(const float* __restrict__ x,
                        const float* __restrict__ wl0, const float* __restrict__ wr0,
                        const float* __restrict__ wl1, const float* __restrict__ wr1,
                        const int* __restrict__ dst) {
    long long gi = (long long)blockIdx.x * 256 + threadIdx.x;
    if (gi < CAST_ITEMS) {
        float2 v = ((const float2*)x)[gi];
        reinterpret_cast<uint32_t*>(g_xbf)[gi] = packbf(v.x, v.y);
    } else if (gi < CAST_ITEMS + EE) {
        int e = (int)(gi - CAST_ITEMS);
        atomicAdd(&g_counts[dst[e]], 1);
    } else if (gi < PREP_TOTAL) {
        int i = (int)(gi - (CAST_ITEMS + EE));   // 0..32767
        int m = i >> 13, idx = i & 8191;
        int n = idx & 127, k2 = idx >> 7;
        const float* s = (m == 0) ? wl0 : (m == 1) ? wr0 : (m == 2) ? wl1 : wr1;
        float2 v = *(const float2*)(s + n * 128 + 2 * k2);
        g_wp[m * 8192 + k2 * 128 + n] = packbf(v.x, v.y);
    }
}

// ---------------- CSR build --------------------------------------------------
// per-block exclusive scan, shfl-based (2 barriers)
__global__ void k_scan1() {
    __shared__ int warpsum[32];
    int t = threadIdx.x;
    int g = blockIdx.x * 1024 + t;
    int v = (g < NN) ? g_counts[g] : 0;
    int lane = t & 31, w = t >> 5;
    int incl = v;
    #pragma unroll
    for (int o = 1; o < 32; o <<= 1) {
        int xx = __shfl_up_sync(0xffffffffu, incl, o);
        if (lane >= o) incl += xx;
    }
    if (lane == 31) warpsum[w] = incl;
    __syncthreads();
    if (w == 0) {
        int s = warpsum[lane];
        #pragma unroll
        for (int o = 1; o < 32; o <<= 1) {
            int xx = __shfl_up_sync(0xffffffffu, s, o);
            if (lane >= o) s += xx;
        }
        warpsum[lane] = s;
    }
    __syncthreads();
    int woff = (w > 0) ? warpsum[w - 1] : 0;
    incl += woff;
    if (g < NN) g_row[g] = incl - v;   // exclusive within block
    if (t == 1023) g_bsums[blockIdx.x] = incl;
}

// scan of block sums done redundantly per block (98 values, trivial) + finalize
__global__ void k_scan3() {
    __shared__ int sb[128];
    int t = threadIdx.x;
    if (t < 128) sb[t] = (t < 98) ? g_bsums[t] : 0;
    __syncthreads();
    #pragma unroll
    for (int off = 1; off < 128; off <<= 1) {
        int x = (t < 128 && t >= off) ? sb[t - off] : 0;
        __syncthreads();
        if (t < 128) sb[t] += x;
        __syncthreads();
    }
    int myoff = (blockIdx.x == 0) ? 0 : sb[blockIdx.x - 1];   // inclusive -> exclusive
    int g = blockIdx.x * 1024 + t;
    if (g < NN) {
        int r = g_row[g] + myoff;
        g_row[g] = r;
        g_cursor[g] = r;
        int c = g_counts[g];
        g_invdeg[g] = 1.0f / (float)(c > 0 ? c : 1);
    }
    if (blockIdx.x == 0 && t == 0) g_row[NN] = EE;
}

__global__ void k_scatter(const int* __restrict__ src, const int* __restrict__ dst) {
    int e = blockIdx.x * blockDim.x + threadIdx.x;
    if (e < EE) {
        int d = dst[e];
        int pos = atomicAdd(&g_cursor[d], 1);
        g_csr[pos] = src[e];
    }
}

// ---------------- standalone bf16 mean aggregation, warp per node -------------
__device__ __forceinline__ void addbf(float4& a, uint2 v) {
    float2 f0 = __bfloat1622float2(*(__nv_bfloat162*)&v.x);
    float2 f1 = __bfloat1622float2(*(__nv_bfloat162*)&v.y);
    a.x += f0.x; a.y += f0.y; a.z += f1.x; a.w += f1.y;
}

__global__ void __launch_bounds__(256) k_aggbf(const __nv_bfloat16* __restrict__ hin,
                                               __nv_bfloat16* __restrict__ aggout) {
    int warp = (blockIdx.x * blockDim.x + threadIdx.x) >> 5;
    int lane = threadIdx.x & 31;
    if (warp >= NN) return;
    const uint2* hin2 = (const uint2*)hin;
    int e = g_row[warp], e1 = g_row[warp + 1];
    float4 a0 = make_float4(0.f, 0.f, 0.f, 0.f);
    float4 a1 = a0, a2 = a0, a3 = a0;
    // 8-way batched loads (MLP=8), 4 accumulators
    for (; e + 7 < e1; e += 8) {
        int i0 = g_csr[e],     i1 = g_csr[e + 1];
        int i2 = g_csr[e + 2], i3 = g_csr[e + 3];
        int i4 = g_csr[e + 4], i5 = g_csr[e + 5];
        int i6 = g_csr[e + 6], i7 = g_csr[e + 7];
        uint2 v0 = hin2[(size_t)i0 * 32 + lane];
        uint2 v1 = hin2[(size_t)i1 * 32 + lane];
        uint2 v2 = hin2[(size_t)i2 * 32 + lane];
        uint2 v3 = hin2[(size_t)i3 * 32 + lane];
        uint2 v4 = hin2[(size_t)i4 * 32 + lane];
        uint2 v5 = hin2[(size_t)i5 * 32 + lane];
        uint2 v6 = hin2[(size_t)i6 * 32 + lane];
        uint2 v7 = hin2[(size_t)i7 * 32 + lane];
        addbf(a0, v0); addbf(a1, v1); addbf(a2, v2); addbf(a3, v3);
        addbf(a0, v4); addbf(a1, v5); addbf(a2, v6); addbf(a3, v7);
    }
    if (e + 3 < e1) {
        int i0 = g_csr[e],     i1 = g_csr[e + 1];
        int i2 = g_csr[e + 2], i3 = g_csr[e + 3];
        uint2 v0 = hin2[(size_t)i0 * 32 + lane];
        uint2 v1 = hin2[(size_t)i1 * 32 + lane];
        uint2 v2 = hin2[(size_t)i2 * 32 + lane];
        uint2 v3 = hin2[(size_t)i3 * 32 + lane];
        addbf(a0, v0); addbf(a1, v1); addbf(a2, v2); addbf(a3, v3);
        e += 4;
    }
    if (e + 1 < e1) {
        uint2 v0 = hin2[(size_t)g_csr[e] * 32 + lane];
        uint2 v1 = hin2[(size_t)g_csr[e + 1] * 32 + lane];
        addbf(a0, v0); addbf(a1, v1);
        e += 2;
    }
    if (e < e1) {
        uint2 v0 = hin2[(size_t)g_csr[e] * 32 + lane];
        addbf(a0, v0);
    }
    float sc4 = g_invdeg[warp];
    float rx = (a0.x + a1.x + a2.x + a3.x) * sc4;
    float ry = (a0.y + a1.y + a2.y + a3.y) * sc4;
    float rz = (a0.z + a1.z + a2.z + a3.z) * sc4;
    float rw = (a0.w + a1.w + a2.w + a3.w) * sc4;
    uint2 o;
    o.x = packbf(rx, ry);
    o.y = packbf(rz, rw);
    ((uint2*)aggout)[(size_t)warp * 32 + lane] = o;
}

// ---------------- layer: cp.async stage + bf16 MMA (+ optional projection) ----
// out = relu(agg@Wl^T + b + hin@Wr^T)
// MODE 0: write 128-dim bf16 result to hout.
// MODE 1: project with wl2/wr2 -> g_pl/g_pr [N,2]; hout untouched.
// W (both K=128 chunks) staged ONCE; X staged per chunk via cp.async.
#define XS2 68    // uint32 (bf16x2) stride: A-frag reads conflict-free
#define WS2 136   // uint32 stride: B-frag reads conflict-free

__device__ __forceinline__ void mma_bf16(float* c, const uint32_t* a, const uint32_t* b) {
    asm volatile(
        "mma.sync.aligned.m16n8k16.row.col.f32.bf16.bf16.f32 "
        "{%0,%1,%2,%3}, {%4,%5,%6,%7}, {%8,%9}, {%0,%1,%2,%3};"
        : "+f"(c[0]), "+f"(c[1]), "+f"(c[2]), "+f"(c[3])
        : "r"(a[0]), "r"(a[1]), "r"(a[2]), "r"(a[3]), "r"(b[0]), "r"(b[1]));
}

__device__ __forceinline__ void cpa16(uint32_t* s, const void* g) {
    uint32_t sa = (uint32_t)__cvta_generic_to_shared(s);
    asm volatile("cp.async.ca.shared.global [%0], [%1], 16;" :: "r"(sa), "l"(g));
}
__device__ __forceinline__ void cpa_commit() {
    asm volatile("cp.async.commit_group;" ::: "memory");
}
__device__ __forceinline__ void cpa_wait0() {
    asm volatile("cp.async.wait_group 0;" ::: "memory");
}

template <int MODE>
__global__ void __launch_bounds__(256, 2) k_layer(
    const __nv_bfloat16* __restrict__ agg, const __nv_bfloat16* __restrict__ hin,
    const uint32_t* __restrict__ wpL, const uint32_t* __restrict__ wpR,
    const float* __restrict__ bias, __nv_bfloat16* __restrict__ hout,
    const float* __restrict__ wl2, const float* __restrict__ wr2) {
    extern __shared__ uint32_t sm[];
    uint32_t* sW = sm;                    // [128][WS2]  (both K-halves)
    uint32_t* sX = sm + 128 * WS2;        // [128][XS2]

    int tid = threadIdx.x;
    int lane = tid & 31, wid = tid >> 5;
    int g = lane >> 2, t = lane & 3;
    int mw = wid & 3, nw = wid >> 2;
    int nodeBase = blockIdx.x * 128;

    float acc[2][8][4];
    #pragma unroll
    for (int i = 0; i < 2; i++)
        #pragma unroll
        for (int j = 0; j < 8; j++)
            #pragma unroll
            for (int q = 0; q < 4; q++) acc[i][j][q] = 0.f;

    // ---- stage both W chunks once (cp.async, 16 x 16B per thread) ----
    #pragma unroll
    for (int i = tid * 4; i < 64 * 128; i += 256 * 4) {
        int k2 = i >> 7, n = i & 127;
        cpa16(&sW[k2 * WS2 + n], wpL + i);
        cpa16(&sW[(k2 + 64) * WS2 + n], wpR + i);
    }

    #pragma unroll
    for (int chunk = 0; chunk < 2; chunk++) {
        // ---- stage X for this chunk (cp.async, 8 x 16B per thread) ----
        const uint32_t* xsrc = (const uint32_t*)(chunk ? hin : agg);
        #pragma unroll
        for (int i = tid * 4; i < 128 * 64; i += 256 * 4) {
            int r = i >> 6, c2 = i & 63;
            int n = nodeBase + r;
            if (n < NN) {
                cpa16(&sX[r * XS2 + c2], xsrc + (size_t)n * 64 + c2);
            } else {
                uint32_t* p = &sX[r * XS2 + c2];
                p[0] = 0; p[1] = 0; p[2] = 0; p[3] = 0;
            }
        }
        cpa_commit();
        cpa_wait0();
        __syncthreads();

        int koff2 = chunk * 64;
        #pragma unroll
        for (int ks = 0; ks < 8; ks++) {
            int k02 = ks * 8;   // col2 units (16 k-elements = 8 pairs)
            uint32_t a[2][4], b[8][2];
            #pragma unroll
            for (int i = 0; i < 2; i++) {
                int row = mw * 32 + i * 16 + g;
                a[i][0] = sX[row * XS2 + k02 + t];
                a[i][1] = sX[(row + 8) * XS2 + k02 + t];
                a[i][2] = sX[row * XS2 + k02 + t + 4];
                a[i][3] = sX[(row + 8) * XS2 + k02 + t + 4];
            }
            #pragma unroll
            for (int j = 0; j < 8; j++) {
                int col = nw * 64 + j * 8 + g;
                b[j][0] = sW[(koff2 + k02 + t) * WS2 + col];
                b[j][1] = sW[(koff2 + k02 + t + 4) * WS2 + col];
            }
            #pragma unroll
            for (int i = 0; i < 2; i++)
                #pragma unroll
                for (int j = 0; j < 8; j++)
                    mma_bf16(acc[i][j], a[i], b[j]);
        }
        __syncthreads();   // MMA done before sX restage / smem reuse
    }

    if (MODE == 0) {
        // epilogue: bias + relu -> bf16 hout
        #pragma unroll
        for (int i = 0; i < 2; i++) {
            int row0 = nodeBase + mw * 32 + i * 16 + g;
            #pragma unroll
            for (int j = 0; j < 8; j++) {
                int col = nw * 64 + j * 8 + 2 * t;
                float2 bb = *(const float2*)(bias + col);
                float v0x = fmaxf(acc[i][j][0] + bb.x, 0.f);
                float v0y = fmaxf(acc[i][j][1] + bb.y, 0.f);
                float v1x = fmaxf(acc[i][j][2] + bb.x, 0.f);
                float v1y = fmaxf(acc[i][j][3] + bb.y, 0.f);
                if (row0 < NN)
                    ((uint32_t*)hout)[(size_t)row0 * 64 + (col >> 1)] = packbf(v0x, v0y);
                if (row0 + 8 < NN)
                    ((uint32_t*)hout)[(size_t)(row0 + 8) * 64 + (col >> 1)] = packbf(v1x, v1y);
            }
        }
    } else {
        // epilogue: bias + relu + project onto wl2/wr2 (fp32)
        float pp[4][4];
        #pragma unroll
        for (int s = 0; s < 4; s++)
            #pragma unroll
            for (int o = 0; o < 4; o++) pp[s][o] = 0.f;

        #pragma unroll
        for (int j = 0; j < 8; j++) {
            int col = nw * 64 + j * 8 + 2 * t;
            float2 bb = *(const float2*)(bias + col);
            float2 wl2a = *(const float2*)(wl2 + col);
            float2 wl2b = *(const float2*)(wl2 + 128 + col);
            float2 wr2a = *(const float2*)(wr2 + col);
            float2 wr2b = *(const float2*)(wr2 + 128 + col);
            #pragma unroll
            for (int i = 0; i < 2; i++) {
                float vx = fmaxf(acc[i][j][0] + bb.x, 0.f);
                float vy = fmaxf(acc[i][j][1] + bb.y, 0.f);
                pp[2*i][0] += vx * wl2a.x + vy * wl2a.y;
                pp[2*i][1] += vx * wl2b.x + vy * wl2b.y;
                pp[2*i][2] += vx * wr2a.x + vy * wr2a.y;
                pp[2*i][3] += vx * wr2b.x + vy * wr2b.y;
                vx = fmaxf(acc[i][j][2] + bb.x, 0.f);
                vy = fmaxf(acc[i][j][3] + bb.y, 0.f);
                pp[2*i+1][0] += vx * wl2a.x + vy * wl2a.y;
                pp[2*i+1][1] += vx * wl2b.x + vy * wl2b.y;
                pp[2*i+1][2] += vx * wr2a.x + vy * wr2a.y;
                pp[2*i+1][3] += vx * wr2b.x + vy * wr2b.y;
            }
        }
        #pragma unroll
        for (int s = 0; s < 4; s++)
            #pragma unroll
            for (int o = 0; o < 4; o++) {
                pp[s][o] += __shfl_xor_sync(0xffffffffu, pp[s][o], 1);
                pp[s][o] += __shfl_xor_sync(0xffffffffu, pp[s][o], 2);
            }
        float* sred = (float*)sm;   // [128][8]
        if (t == 0) {
            #pragma unroll
            for (int s = 0; s < 4; s++) {
                int lr = mw * 32 + s * 8 + g;
                #pragma unroll
                for (int o = 0; o < 4; o++) sred[lr * 8 + nw * 4 + o] = pp[s][o];
            }
        }
        __syncthreads();
        if (tid < 128) {
            int node = nodeBase + tid;
            if (node < NN) {
                float pl0 = sred[tid * 8 + 0] + sred[tid * 8 + 4];
                float pl1 = sred[tid * 8 + 1] + sred[tid * 8 + 5];
                float pr0 = sred[tid * 8 + 2] + sred[tid * 8 + 6];
                float pr1 = sred[tid * 8 + 3] + sred[tid * 8 + 7];
                *(float2*)&g_pl[node * 2] = make_float2(pl0, pl1);
                *(float2*)&g_pr[node * 2] = make_float2(pr0, pr1);
            }
        }
    }
}

// ---------------- layer 2 aggregation (2-dim) + bias + log_softmax ------------
__global__ void k_final(const float* __restrict__ b2, float* __restrict__ out) {
    int warp = (blockIdx.x * blockDim.x + threadIdx.x) >> 5;
    int lane = threadIdx.x & 31;
    if (warp >= NN) return;
    int s0 = g_row[warp];
    int s1 = g_row[warp + 1];
    float a0 = 0.f, a1 = 0.f;
    for (int e = s0 + lane; e < s1; e += 32) {
        int s = g_csr[e];
        float2 v = *(const float2*)&g_pl[s * 2];
        a0 += v.x;
        a1 += v.y;
    }
    #pragma unroll
    for (int o = 16; o; o >>= 1) {
        a0 += __shfl_xor_sync(0xffffffffu, a0, o);
        a1 += __shfl_xor_sync(0xffffffffu, a1, o);
    }
    if (lane == 0) {
        float inv = g_invdeg[warp];
        float o0 = a0 * inv + b2[0] + g_pr[warp * 2 + 0];
        float o1 = a1 * inv + b2[1] + g_pr[warp * 2 + 1];
        float m = fmaxf(o0, o1);
        float ls = m + logf(expf(o0 - m) + expf(o1 - m));
        out[warp * 2 + 0] = o0 - ls;
        out[warp * 2 + 1] = o1 - ls;
    }
}

// ---------------- launch -----------------------------------------------------
extern "C" void kernel_launch(void* const* d_in, const int* in_sizes, int n_in,
                              void* d_out, int out_size) {
    const float* x    = (const float*)d_in[0];
    const float* wl0  = (const float*)d_in[1];
    const float* b0   = (const float*)d_in[2];
    const float* wr0  = (const float*)d_in[3];
    const float* wl1  = (const float*)d_in[4];
    const float* b1   = (const float*)d_in[5];
    const float* wr1  = (const float*)d_in[6];
    const float* wl2  = (const float*)d_in[7];
    const float* b2   = (const float*)d_in[8];
    const float* wr2  = (const float*)d_in[9];
    const int* esrc   = (const int*)d_in[10];
    const int* edst   = (const int*)d_in[11];
    float* out        = (float*)d_out;

    __nv_bfloat16* xbf;   cudaGetSymbolAddress((void**)&xbf, g_xbf);
    __nv_bfloat16* h1bf;  cudaGetSymbolAddress((void**)&h1bf, g_h1bf);
    __nv_bfloat16* aggbf; cudaGetSymbolAddress((void**)&aggbf, g_aggbf);
    uint32_t* wp;         cudaGetSymbolAddress((void**)&wp, g_wp);

    const int nblk_scan = (NN + 1023) / 1024;        // 98
    const int layer_smem = (128 * WS2 + 128 * XS2) * (int)sizeof(uint32_t);  // 104448
    cudaFuncSetAttribute(k_layer<0>, cudaFuncAttributeMaxDynamicSharedMemorySize, layer_smem);
    cudaFuncSetAttribute(k_layer<1>, cudaFuncAttributeMaxDynamicSharedMemorySize, layer_smem);

    const int gemm_blocks = (NN + 127) / 128;        // 782
    const int agg_blocks = (NN + 7) / 8;             // warp per node
    const int prep_blocks = (PREP_TOTAL + 255) / 256;

    // 1: zero counts
    k_zero<<<nblk_scan, 1024>>>();
    // 2: merged cast + weight-pack + histogram
    k_prep2<<<prep_blocks, 256>>>(x, wl0, wr0, wl1, wr1, edst);
    // 3-5: scan + scatter
    k_scan1<<<nblk_scan, 1024>>>();
    k_scan3<<<nblk_scan, 1024>>>();
    k_scatter<<<(EE + 255) / 256, 256>>>(esrc, edst);
    // 6: Layer 0 aggregation (L2-bandwidth bound)
    k_aggbf<<<agg_blocks, 256>>>(xbf, aggbf);
    // 7: Layer 0 stage+MMA -> h1 (bf16)
    k_layer<0><<<gemm_blocks, 256, layer_smem>>>(aggbf, xbf, wp, wp + 8192, b0, h1bf, nullptr, nullptr);
    // 8: Layer 1 aggregation
    k_aggbf<<<agg_blocks, 256>>>(h1bf, aggbf);
    // 9: Layer 1 stage+MMA + output projection -> g_pl/g_pr
    k_layer<1><<<gemm_blocks, 256, layer_smem>>>(aggbf, h1bf, wp + 16384, wp + 24576, b1, nullptr, wl2, wr2);
    // 10: Layer 2: 2-dim aggregation + bias + log_softmax
    k_final<<<agg_blocks, 256>>>(b2, out);
}